// round 13
// baseline (speedup 1.0000x reference)
#include <cuda_runtime.h>
#include <float.h>
#include <math.h>

#define BATCH 4
#define NPTS  2048
#define KNN   80
#define FEAT  256
#define MLPO  1024
#define EPSV  1e-5f
#define KC    16         // GEMM K-chunk
#define KCP   20         // smem row stride for K-chunk tiles
#define CAP   256        // per-warp candidate list capacity (fallback beyond)

// ---------------- scratch (static device globals; no allocation) ----------------
__device__ float    g_xt[BATCH*NPTS*3];
__device__ __align__(16) unsigned g_key[(size_t)BATCH*NPTS*NPTS];  // 64 MB key scratch
__device__ int      g_idx[BATCH*NPTS*KNN];
__device__ float    g_sq[BATCH*NPTS];
__device__ __align__(16) float g_y[BATCH*NPTS*128];
__device__ __align__(16) float g_c[BATCH*NPTS*128];
__device__ __align__(16) float g_hmax[BATCH*NPTS*128];
__device__ __align__(16) float g_hmin[BATCH*NPTS*128];
__device__ float    g_pst[BATCH*NPTS*4*2];
__device__ float    g_ss[BATCH*MLPO*2];
__device__ float    g_feats[BATCH*NPTS*FEAT];
__device__ __align__(16) float g_fhi[BATCH*NPTS*FEAT];   // tf32-hi of feats
__device__ __align__(16) float g_flo[BATCH*NPTS*FEAT];   // tf32-lo of feats
__device__ __align__(16) float g_wmhi[MLPO*FEAT];        // tf32-hi of Wm
__device__ __align__(16) float g_wmlo[MLPO*FEAT];        // tf32-lo of Wm
__device__ float    g_h[(size_t)BATCH*NPTS*MLPO];
__device__ float    g_mmax[BATCH*8*MLPO];
__device__ float    g_mmin[BATCH*8*MLPO];
__device__ float    g_gp[BATCH*8*8*2];
__device__ float    g_wlt[3][64*128];                 // transposed Wl  [c][o]
__device__ float    g_wdt[3][64*128];                 // transposed Wr-Wl [c][o]

// ---------------- helpers ----------------
__device__ __forceinline__ unsigned f2u(float f) {
    unsigned u = __float_as_uint(f);
    return (u & 0x80000000u) ? ~u : (u | 0x80000000u);
}

__device__ __forceinline__ void mma_tf32(float c[4], unsigned a0, unsigned a1,
                                         unsigned a2, unsigned a3,
                                         unsigned b0, unsigned b1) {
    asm volatile(
        "mma.sync.aligned.m16n8k8.row.col.f32.tf32.tf32.f32 "
        "{%0,%1,%2,%3}, {%4,%5,%6,%7}, {%8,%9}, {%0,%1,%2,%3};\n"
        : "+f"(c[0]), "+f"(c[1]), "+f"(c[2]), "+f"(c[3])
        : "r"(a0), "r"(a1), "r"(a2), "r"(a3), "r"(b0), "r"(b1));
}

__device__ __forceinline__ void tf32split(float v, unsigned& hi, unsigned& lo) {
    unsigned h;
    asm("cvt.rna.tf32.f32 %0, %1;" : "=r"(h) : "f"(v));
    float hf = __uint_as_float(h);
    asm("cvt.rna.tf32.f32 %0, %1;" : "=r"(lo) : "f"(v - hf));
    hi = h;
}

__device__ __forceinline__ int warp_excl_scan(int v, int lane, int& tot) {
    int x = v;
    #pragma unroll
    for (int off = 1; off < 32; off <<= 1) {
        int t = __shfl_up_sync(0xFFFFFFFFu, x, off);
        if (lane >= off) x += t;
    }
    tot = __shfl_sync(0xFFFFFFFFu, x, 31);
    return x - v;
}

// ---------------- transpose x [B,3,N] -> xt [B,N,3] ----------------
__global__ void k_transpose(const float* __restrict__ x) {
    int i = blockIdx.x * 256 + threadIdx.x;
    if (i < BATCH*3*NPTS) {
        int b = i / (3*NPTS);
        int r = i % (3*NPTS);
        int c = r / NPTS, n = r % NPTS;
        g_xt[(b*NPTS + n)*3 + c] = x[i];
    }
}

// ---------------- weight transpose: W[o][2C] -> wlt[c][o], wdt[c][o] ----------------
__global__ void k_wt(const float* __restrict__ W1, const float* __restrict__ W2,
                     const float* __restrict__ W3) {
    int i = blockIdx.x * 256 + threadIdx.x;
    if (i < 3*64) {
        int c = i / 64, o = i % 64;
        float wl = W1[o*6 + c];
        g_wlt[0][c*64 + o] = wl;
        g_wdt[0][c*64 + o] = W1[o*6 + 3 + c] - wl;
    }
    if (i < 64*64) {
        int c = i / 64, o = i % 64;
        float wl = W2[o*128 + c];
        g_wlt[1][c*64 + o] = wl;
        g_wdt[1][c*64 + o] = W2[o*128 + 64 + c] - wl;
    }
    if (i < 64*128) {
        int c = i >> 7, o = i & 127;
        float wl = W3[o*128 + c];
        g_wlt[2][c*128 + o] = wl;
        g_wdt[2][c*128 + o] = W3[o*128 + 64 + c] - wl;
    }
}

// ---------------- Wm pre-split into tf32 hi/lo ----------------
__global__ void k_wsplit(const float* __restrict__ Wm) {
    int i = blockIdx.x * 256 + threadIdx.x;
    if (i < MLPO*FEAT) {
        unsigned hi, lo;
        tf32split(Wm[i], hi, lo);
        g_wmhi[i] = __uint_as_float(hi);
        g_wmlo[i] = __uint_as_float(lo);
    }
}

// ---------------- layer-1 keys: g_key[b,n,m] = f2u(2*<x_n,x_m> - |x_m|^2) ----------
__global__ void __launch_bounds__(256) k_keys3() {
    __shared__ float sx[NPTS], sy[NPTS], sz[NPTS], sq[NPTS];
    int b = blockIdx.y;
    int n0 = blockIdx.x * 8;
    int tid = threadIdx.x;
    const float* base = &g_xt[(b*NPTS)*3];
    for (int i = tid; i < NPTS; i += 256) {
        float X = base[i*3], Y = base[i*3+1], Z = base[i*3+2];
        sx[i] = X; sy[i] = Y; sz[i] = Z;
        sq[i] = X*X + Y*Y + Z*Z;
    }
    __syncthreads();
    #pragma unroll
    for (int r = 0; r < 8; r++) {
        int n = n0 + r;
        float cx = sx[n], cy = sy[n], cz = sz[n];
        unsigned* row = &g_key[((size_t)(b*NPTS + n))*NPTS];
        for (int m = tid; m < NPTS; m += 256) {
            float key = 2.f*(cx*sx[m] + cy*sy[m] + cz*sz[m]) - sq[m];
            row[m] = f2u(key);
        }
    }
}

// ---------------- squared norms of feature rows ----------------
__global__ void k_sq(int foff) {
    int p = blockIdx.x * 8 + (threadIdx.x >> 5);
    int lane = threadIdx.x & 31;
    if (p < BATCH*NPTS) {
        const float* r = &g_feats[(size_t)p*FEAT + foff];
        float v = r[lane], w = r[lane + 32];
        float s = v*v + w*w;
        #pragma unroll
        for (int o = 16; o; o >>= 1) s += __shfl_xor_sync(~0u, s, o);
        if (lane == 0) g_sq[p] = s;
    }
}

// ---------------- warp top-80 radix select over a GLOBAL key row (3-scan) ----------
__device__ __forceinline__ void warp_topk80_g(const uint4* __restrict__ sk4,
                                              int* __restrict__ hist,
                                              unsigned* __restrict__ cand, int p) {
    const unsigned FULL = 0xFFFFFFFFu;
    int lane = threadIdx.x & 31;
    unsigned prefix = 0, maskacc = 0;
    int kneed = KNN;
    #pragma unroll
    for (int pass = 0; pass < 2; pass++) {
        int shift = 24 - 8*pass;
        #pragma unroll
        for (int i = 0; i < 8; i++) hist[lane*8 + i] = 0;
        __syncwarp();
        #pragma unroll 4
        for (int v = 0; v < 16; v++) {
            uint4 q = sk4[(v << 5) + lane];
            if ((q.x & maskacc) == prefix) atomicAdd(&hist[(q.x >> shift) & 255], 1);
            if ((q.y & maskacc) == prefix) atomicAdd(&hist[(q.y >> shift) & 255], 1);
            if ((q.z & maskacc) == prefix) atomicAdd(&hist[(q.z >> shift) & 255], 1);
            if ((q.w & maskacc) == prefix) atomicAdd(&hist[(q.w >> shift) & 255], 1);
        }
        __syncwarp();
        int h[8], lsum = 0;
        #pragma unroll
        for (int i = 0; i < 8; i++) { h[i] = hist[lane*8 + i]; lsum += h[i]; }
        int v = lsum;
        #pragma unroll
        for (int off = 1; off < 32; off <<= 1) {
            int t = __shfl_down_sync(FULL, v, off);
            if (lane < 32 - off) v += t;
        }
        int run = v - lsum;
        int selbyte = -1, selrem = 0;
        #pragma unroll
        for (int i = 7; i >= 0; i--) {
            int incl = run + h[i];
            if (run < kneed && kneed <= incl) { selbyte = lane*8 + i; selrem = kneed - run; }
            run = incl;
        }
        unsigned ball = __ballot_sync(FULL, selbyte >= 0);
        int srcl = __ffs(ball) - 1;
        selbyte = __shfl_sync(FULL, selbyte, srcl);
        selrem  = __shfl_sync(FULL, selrem,  srcl);
        prefix |= ((unsigned)selbyte) << shift;
        maskacc |= (0xFFu << shift);
        kneed = selrem;
        __syncwarp();
    }
    unsigned pref16 = prefix >> 16;
    int* out = &g_idx[p*KNN];
    int totG = KNN - kneed;
    int baseG = 0, nl = 0;
    #pragma unroll 1
    for (int v = 0; v < 16; v++) {
        uint4 q = sk4[(v << 5) + lane];
        int i0 = ((v << 5) + lane) << 2;
        unsigned ks[4] = {q.x, q.y, q.z, q.w};
        #pragma unroll
        for (int e = 0; e < 4; e++) {
            unsigned u = ks[e];
            unsigned h16 = u >> 16;
            bool gt = h16 > pref16;
            bool eq = h16 == pref16;
            unsigned bg = __ballot_sync(FULL, gt);
            unsigned be = __ballot_sync(FULL, eq);
            unsigned lt = (1u << lane) - 1u;
            if (gt) out[baseG + __popc(bg & lt)] = i0 + e;
            if (eq) {
                int pos = nl + __popc(be & lt);
                if (pos < CAP)
                    cand[pos] = ((u & 0xFFFFu) << 16) | (unsigned)(2047 - (i0 + e));
            }
            baseG += __popc(bg);
            nl += __popc(be);
        }
    }
    __syncwarp();
    if (nl <= CAP) {
        for (int i = lane; i < nl; i += 32) {
            unsigned mine = cand[i];
            int rank = 0;
            for (int j = 0; j < nl; j++) rank += (cand[j] > mine);
            if (rank < kneed) out[totG + rank] = 2047 - (int)(mine & 0xFFFFu);
        }
    } else {
        #pragma unroll
        for (int pass = 0; pass < 2; pass++) {
            int shift = 8 - 8*pass;
            #pragma unroll
            for (int i = 0; i < 8; i++) hist[lane*8 + i] = 0;
            __syncwarp();
            #pragma unroll 4
            for (int v = 0; v < 16; v++) {
                uint4 q = sk4[(v << 5) + lane];
                if ((q.x & maskacc) == prefix) atomicAdd(&hist[(q.x >> shift) & 255], 1);
                if ((q.y & maskacc) == prefix) atomicAdd(&hist[(q.y >> shift) & 255], 1);
                if ((q.z & maskacc) == prefix) atomicAdd(&hist[(q.z >> shift) & 255], 1);
                if ((q.w & maskacc) == prefix) atomicAdd(&hist[(q.w >> shift) & 255], 1);
            }
            __syncwarp();
            int h[8], lsum = 0;
            #pragma unroll
            for (int i = 0; i < 8; i++) { h[i] = hist[lane*8 + i]; lsum += h[i]; }
            int v = lsum;
            #pragma unroll
            for (int off = 1; off < 32; off <<= 1) {
                int t = __shfl_down_sync(FULL, v, off);
                if (lane < 32 - off) v += t;
            }
            int run = v - lsum;
            int selbyte = -1, selrem = 0;
            #pragma unroll
            for (int i = 7; i >= 0; i--) {
                int incl = run + h[i];
                if (run < kneed && kneed <= incl) { selbyte = lane*8 + i; selrem = kneed - run; }
                run = incl;
            }
            unsigned ball = __ballot_sync(FULL, selbyte >= 0);
            int srcl = __ffs(ball) - 1;
            selbyte = __shfl_sync(FULL, selbyte, srcl);
            selrem  = __shfl_sync(FULL, selrem,  srcl);
            prefix |= ((unsigned)selbyte) << shift;
            maskacc |= (0xFFu << shift);
            kneed = selrem;
            __syncwarp();
        }
        unsigned T = prefix;
        int totG2 = KNN - kneed;
        int bG = 0, bE = 0;
        #pragma unroll 1
        for (int v = 0; v < 16; v++) {
            uint4 q = sk4[(v << 5) + lane];
            int i0 = ((v << 5) + lane) << 2;
            int cg = (q.x > T) + (q.y > T) + (q.z > T) + (q.w > T);
            int totg;
            int pre = warp_excl_scan(cg, lane, totg);
            if (totg) {
                int off = bG + pre;
                if (q.x > T) out[off++] = i0;
                if (q.y > T) out[off++] = i0 + 1;
                if (q.z > T) out[off++] = i0 + 2;
                if (q.w > T) out[off++] = i0 + 3;
                bG += totg;
            }
            int ce = (q.x == T) + (q.y == T) + (q.z == T) + (q.w == T);
            unsigned be2 = __ballot_sync(FULL, ce > 0);
            if (be2) {
                int tote;
                int preE = warp_excl_scan(ce, lane, tote);
                int pos = bE + preE;
                if (q.x == T) { if (pos < kneed) out[totG2 + pos] = i0;     pos++; }
                if (q.y == T) { if (pos < kneed) out[totG2 + pos] = i0 + 1; pos++; }
                if (q.z == T) { if (pos < kneed) out[totG2 + pos] = i0 + 2; pos++; }
                if (q.w == T) { if (pos < kneed) out[totG2 + pos] = i0 + 3; pos++; }
                bE += tote;
            }
        }
    }
}

// ---------------- kNN (all layers): 8 warps/block, keys from g_key ----------------
__global__ void __launch_bounds__(256) k_knn_g() {
    __shared__ int      shist[8][256];   // 8 KB
    __shared__ unsigned scand[8][CAP];   // 8 KB
    int w = threadIdx.x >> 5;
    int p = blockIdx.x * 8 + w;          // b*N + n
    const uint4* row4 = (const uint4*)&g_key[(size_t)p*NPTS];
    warp_topk80_g(row4, shist[w], scand[w], p);
}

// ---------------- key GEMM (tensor core, 3xTF32, pre-split operands) --------------
__global__ void __launch_bounds__(256) k_key_gemm_tc(int foff) {
    __shared__ float Ah[128*KCP], Al[128*KCP], Bh[128*KCP], Bl[128*KCP];
    int b = blockIdx.z;
    int row0 = blockIdx.y * 128, col0 = blockIdx.x * 128;
    int tid = threadIdx.x;
    int wid = tid >> 5, lane = tid & 31;
    int wm = wid >> 2, wn = wid & 3;
    int gid = lane >> 2, tig = lane & 3;
    float acc[4][4][4];
    #pragma unroll
    for (int mt = 0; mt < 4; mt++)
        #pragma unroll
        for (int nt = 0; nt < 4; nt++)
            #pragma unroll
            for (int q = 0; q < 4; q++) acc[mt][nt][q] = 0.f;

    for (int ch = 0; ch < 64/KC; ch++) {
        const float* Agh = &g_fhi[(size_t)(b*NPTS + row0)*FEAT + foff + ch*KC];
        const float* Agl = &g_flo[(size_t)(b*NPTS + row0)*FEAT + foff + ch*KC];
        const float* Bgh = &g_fhi[(size_t)(b*NPTS + col0)*FEAT + foff + ch*KC];
        const float* Bgl = &g_flo[(size_t)(b*NPTS + col0)*FEAT + foff + ch*KC];
        #pragma unroll
        for (int i = 0; i < 2; i++) {
            int idx = tid + 256*i;                 // 512 float4 per tile
            int r = idx >> 2, c = (idx & 3) << 2;
            *(float4*)&Ah[r*KCP + c] = *(const float4*)(Agh + (size_t)r*FEAT + c);
            *(float4*)&Al[r*KCP + c] = *(const float4*)(Agl + (size_t)r*FEAT + c);
            *(float4*)&Bh[r*KCP + c] = *(const float4*)(Bgh + (size_t)r*FEAT + c);
            *(float4*)&Bl[r*KCP + c] = *(const float4*)(Bgl + (size_t)r*FEAT + c);
        }
        __syncthreads();
        #pragma unroll
        for (int ks = 0; ks < 2; ks++) {
            int k0 = ks*8;
            unsigned bhi[4][2], blo[4][2];
            #pragma unroll
            for (int nt = 0; nt < 4; nt++) {
                int rB = (wn*32 + nt*8 + gid)*KCP + k0 + tig;
                bhi[nt][0] = __float_as_uint(Bh[rB]);
                bhi[nt][1] = __float_as_uint(Bh[rB + 4]);
                blo[nt][0] = __float_as_uint(Bl[rB]);
                blo[nt][1] = __float_as_uint(Bl[rB + 4]);
            }
            #pragma unroll
            for (int mt = 0; mt < 4; mt++) {
                int rA = (wm*64 + mt*16 + gid)*KCP + k0 + tig;
                unsigned ah[4], al[4];
                ah[0] = __float_as_uint(Ah[rA]);
                ah[1] = __float_as_uint(Ah[rA + 8*KCP]);
                ah[2] = __float_as_uint(Ah[rA + 4]);
                ah[3] = __float_as_uint(Ah[rA + 8*KCP + 4]);
                al[0] = __float_as_uint(Al[rA]);
                al[1] = __float_as_uint(Al[rA + 8*KCP]);
                al[2] = __float_as_uint(Al[rA + 4]);
                al[3] = __float_as_uint(Al[rA + 8*KCP + 4]);
                #pragma unroll
                for (int nt = 0; nt < 4; nt++) {
                    mma_tf32(acc[mt][nt], ah[0], ah[1], ah[2], ah[3], bhi[nt][0], bhi[nt][1]);
                    mma_tf32(acc[mt][nt], ah[0], ah[1], ah[2], ah[3], blo[nt][0], blo[nt][1]);
                    mma_tf32(acc[mt][nt], al[0], al[1], al[2], al[3], bhi[nt][0], bhi[nt][1]);
                }
            }
        }
        __syncthreads();
    }
    const float* sqb = &g_sq[b*NPTS];
    unsigned* keyb = &g_key[(size_t)b*NPTS*NPTS];
    #pragma unroll
    for (int mt = 0; mt < 4; mt++) {
        int rg = row0 + wm*64 + mt*16 + gid;
        #pragma unroll
        for (int nt = 0; nt < 4; nt++) {
            int cg = col0 + wn*32 + nt*8 + tig*2;
            float s0 = sqb[cg], s1 = sqb[cg+1];
            uint2 v0 = make_uint2(f2u(2.f*acc[mt][nt][0] - s0),
                                  f2u(2.f*acc[mt][nt][1] - s1));
            uint2 v1 = make_uint2(f2u(2.f*acc[mt][nt][2] - s0),
                                  f2u(2.f*acc[mt][nt][3] - s1));
            *(uint2*)&keyb[(size_t)rg*NPTS + cg] = v0;
            *(uint2*)&keyb[(size_t)(rg+8)*NPTS + cg] = v1;
        }
    }
}

// ---------------- MLP GEMM (tensor core, 3xTF32, pre-split operands) --------------
__global__ void __launch_bounds__(256) k_mlp_gemm_tc(const float* __restrict__ bm) {
    __shared__ float Ah[128*KCP], Al[128*KCP], Bh[128*KCP], Bl[128*KCP];
    int row0 = blockIdx.y * 128, col0 = blockIdx.x * 128;
    int tid = threadIdx.x;
    int wid = tid >> 5, lane = tid & 31;
    int wm = wid >> 2, wn = wid & 3;
    int gid = lane >> 2, tig = lane & 3;
    float acc[4][4][4];
    #pragma unroll
    for (int mt = 0; mt < 4; mt++)
        #pragma unroll
        for (int nt = 0; nt < 4; nt++)
            #pragma unroll
            for (int q = 0; q < 4; q++) acc[mt][nt][q] = 0.f;

    for (int ch = 0; ch < FEAT/KC; ch++) {
        const float* Agh = &g_fhi[(size_t)row0*FEAT + ch*KC];
        const float* Agl = &g_flo[(size_t)row0*FEAT + ch*KC];
        const float* Bgh = &g_wmhi[(size_t)col0*FEAT + ch*KC];
        const float* Bgl = &g_wmlo[(size_t)col0*FEAT + ch*KC];
        #pragma unroll
        for (int i = 0; i < 2; i++) {
            int idx = tid + 256*i;
            int r = idx >> 2, c = (idx & 3) << 2;
            *(float4*)&Ah[r*KCP + c] = *(const float4*)(Agh + (size_t)r*FEAT + c);
            *(float4*)&Al[r*KCP + c] = *(const float4*)(Agl + (size_t)r*FEAT + c);
            *(float4*)&Bh[r*KCP + c] = *(const float4*)(Bgh + (size_t)r*FEAT + c);
            *(float4*)&Bl[r*KCP + c] = *(const float4*)(Bgl + (size_t)r*FEAT + c);
        }
        __syncthreads();
        #pragma unroll
        for (int ks = 0; ks < 2; ks++) {
            int k0 = ks*8;
            unsigned bhi[4][2], blo[4][2];
            #pragma unroll
            for (int nt = 0; nt < 4; nt++) {
                int rB = (wn*32 + nt*8 + gid)*KCP + k0 + tig;
                bhi[nt][0] = __float_as_uint(Bh[rB]);
                bhi[nt][1] = __float_as_uint(Bh[rB + 4]);
                blo[nt][0] = __float_as_uint(Bl[rB]);
                blo[nt][1] = __float_as_uint(Bl[rB + 4]);
            }
            #pragma unroll
            for (int mt = 0; mt < 4; mt++) {
                int rA = (wm*64 + mt*16 + gid)*KCP + k0 + tig;
                unsigned ah[4], al[4];
                ah[0] = __float_as_uint(Ah[rA]);
                ah[1] = __float_as_uint(Ah[rA + 8*KCP]);
                ah[2] = __float_as_uint(Ah[rA + 4]);
                ah[3] = __float_as_uint(Ah[rA + 8*KCP + 4]);
                al[0] = __float_as_uint(Al[rA]);
                al[1] = __float_as_uint(Al[rA + 8*KCP]);
                al[2] = __float_as_uint(Al[rA + 4]);
                al[3] = __float_as_uint(Al[rA + 8*KCP + 4]);
                #pragma unroll
                for (int nt = 0; nt < 4; nt++) {
                    mma_tf32(acc[mt][nt], ah[0], ah[1], ah[2], ah[3], bhi[nt][0], bhi[nt][1]);
                    mma_tf32(acc[mt][nt], ah[0], ah[1], ah[2], ah[3], blo[nt][0], blo[nt][1]);
                    mma_tf32(acc[mt][nt], al[0], al[1], al[2], al[3], bhi[nt][0], bhi[nt][1]);
                }
            }
        }
        __syncthreads();
    }
    #pragma unroll
    for (int mt = 0; mt < 4; mt++) {
        int rg = row0 + wm*64 + mt*16 + gid;
        #pragma unroll
        for (int nt = 0; nt < 4; nt++) {
            int cg = col0 + wn*32 + nt*8 + tig*2;
            float b0 = bm[cg], b1 = bm[cg+1];
            float2 v0 = make_float2(acc[mt][nt][0] + b0, acc[mt][nt][1] + b1);
            float2 v1 = make_float2(acc[mt][nt][2] + b0, acc[mt][nt][3] + b1);
            *(float2*)&g_h[(size_t)rg*MLPO + cg] = v0;
            *(float2*)&g_h[(size_t)(rg+8)*MLPO + cg] = v1;
        }
    }
}

// ---------------- prep: y = f@Wl^T, c = f@(Wr-Wl)^T  (transposed weights) ----------
__global__ void k_prep(int layer, int use_xt, int foff, int Cin, int O) {
    __shared__ float sf[16*64];
    int p0 = blockIdx.x * 16;
    int tid = threadIdx.x;
    for (int i = tid; i < 16*Cin; i += O) {
        int rr = i / Cin, cc = i % Cin;
        int p = p0 + rr;
        sf[rr*Cin + cc] = use_xt ? g_xt[p*3 + cc]
                                 : g_feats[(size_t)p*FEAT + foff + cc];
    }
    __syncthreads();
    float y[16], c2[16];
    #pragma unroll
    for (int r = 0; r < 16; r++) { y[r] = 0.f; c2[r] = 0.f; }
    const float* wl = &g_wlt[layer][tid];
    const float* wd = &g_wdt[layer][tid];
    for (int c = 0; c < Cin; c++) {
        float a = wl[c*O];
        float d = wd[c*O];
        #pragma unroll
        for (int r = 0; r < 16; r++) {
            float fv = sf[r*Cin + c];
            y[r]  += fv * a;
            c2[r] += fv * d;
        }
    }
    #pragma unroll
    for (int r = 0; r < 16; r++) {
        g_y[(size_t)(p0 + r)*O + tid] = y[r];
        g_c[(size_t)(p0 + r)*O + tid] = c2[r];
    }
}

// ---------------- edge pass (float2, warp-per-point) ----------------
__global__ void __launch_bounds__(128) k_edge(int O) {
    __shared__ int sidx[4][KNN];
    int tid = threadIdx.x, wid = tid >> 5, lane = tid & 31;
    int wpp = O >> 6;                      // warps per point
    int ppb = 4 / wpp;                     // points per block
    int p = blockIdx.x * ppb + wid / wpp;
    int wip = wid % wpp;
    for (int i = lane; i < KNN; i += 32)
        sidx[wid][i] = g_idx[p*KNN + i];
    __syncwarp();
    int b = p >> 11;
    int ch = wip*64 + 2*lane;
    int halfO = O >> 1;
    const float2* ybase = (const float2*)&g_y[((size_t)b*NPTS)*O];
    float2 c = *(const float2*)&g_c[(size_t)p*O + ch];
    const int* si = sidx[wid];
    float mx0 = -FLT_MAX, mx1 = -FLT_MAX, mn0 = FLT_MAX, mn1 = FLT_MAX;
    float s = 0.f, ss = 0.f;
    int co = ch >> 1;
    #pragma unroll 4
    for (int k = 0; k < KNN; k++) {
        int j = si[k];
        float2 v = ybase[(size_t)j*halfO + co];
        float v0 = v.x + c.x, v1 = v.y + c.y;
        mx0 = fmaxf(mx0, v0); mn0 = fminf(mn0, v0);
        mx1 = fmaxf(mx1, v1); mn1 = fminf(mn1, v1);
        s += v0 + v1;
        ss += v0*v0 + v1*v1;
    }
    #pragma unroll
    for (int o = 8; o; o >>= 1) {
        s  += __shfl_xor_sync(0xFFFFFFFFu, s,  o);
        ss += __shfl_xor_sync(0xFFFFFFFFu, ss, o);
    }
    int G = O >> 5;
    int g = wip*2 + (lane >> 4);
    if ((lane & 15) == 0) {
        g_pst[((size_t)p*G + g)*2 + 0] = s;
        g_pst[((size_t)p*G + g)*2 + 1] = ss;
    }
    *(float2*)&g_hmax[(size_t)p*O + ch] = make_float2(mx0, mx1);
    *(float2*)&g_hmin[(size_t)p*O + ch] = make_float2(mn0, mn1);
}

// ---------------- GN stats reduce ----------------
__global__ void k_gnstats(int G, int O, const float* __restrict__ gamma,
                          const float* __restrict__ beta) {
    int b = blockIdx.x / G, g = blockIdx.x % G;
    int tid = threadIdx.x;
    float s = 0.f, ss = 0.f;
    for (int n = tid; n < NPTS; n += 256) {
        size_t base = (((size_t)(b*NPTS + n))*G + g)*2;
        s += g_pst[base]; ss += g_pst[base + 1];
    }
    __shared__ float rs[256], rss[256];
    rs[tid] = s; rss[tid] = ss;
    __syncthreads();
    for (int off = 128; off; off >>= 1) {
        if (tid < off) { rs[tid] += rs[tid+off]; rss[tid] += rss[tid+off]; }
        __syncthreads();
    }
    float invc = 1.f / ((float)NPTS * (float)KNN * 32.f);
    float mean = rs[0] * invc;
    float var  = rss[0] * invc - mean*mean;
    float r = rsqrtf(var + EPSV);
    if (tid < 32) {
        int o = g*32 + tid;
        float sg = gamma[o] * r;
        float tt = beta[o] - sg * mean;
        g_ss[(b*O + o)*2 + 0] = sg;
        g_ss[(b*O + o)*2 + 1] = tt;
    }
}

// ---------------- finalize: write feats + tf32 hi/lo splits ----------------
__global__ void k_edge_final(int O, int off) {
    int i = blockIdx.x*256 + threadIdx.x;
    if (i < BATCH*NPTS*O) {
        int p = i / O, o = i % O;
        int b = p >> 11;
        float sg = g_ss[(b*O + o)*2], tt = g_ss[(b*O + o)*2 + 1];
        float h = (sg >= 0.f) ? g_hmax[i] : g_hmin[i];
        float v = sg*h + tt;
        v = (v > 0.f) ? v : 0.2f*v;
        size_t fi = (size_t)p*FEAT + off + o;
        g_feats[fi] = v;
        unsigned hi, lo;
        tf32split(v, hi, lo);
        g_fhi[fi] = __uint_as_float(hi);
        g_flo[fi] = __uint_as_float(lo);
    }
}

// ---------------- MLP head partials ----------------
__global__ void k_mlp_part() {
    int b = blockIdx.z, g = blockIdx.y, seg = blockIdx.x;
    int t = threadIdx.x;
    float mx = -FLT_MAX, mn = FLT_MAX, s = 0.f, ss = 0.f;
    int o = g*128 + t;
    for (int n = seg*256; n < seg*256 + 256; n++) {
        float v = g_h[((size_t)(b*NPTS + n))*MLPO + o];
        mx = fmaxf(mx, v); mn = fminf(mn, v);
        s += v; ss += v*v;
    }
    g_mmax[(b*8 + seg)*MLPO + o] = mx;
    g_mmin[(b*8 + seg)*MLPO + o] = mn;
    __shared__ float rs[128], rss[128];
    rs[t] = s; rss[t] = ss;
    __syncthreads();
    for (int off = 64; off; off >>= 1) {
        if (t < off) { rs[t] += rs[t+off]; rss[t] += rss[t+off]; }
        __syncthreads();
    }
    if (t == 0) {
        g_gp[((b*8 + g)*8 + seg)*2 + 0] = rs[0];
        g_gp[((b*8 + g)*8 + seg)*2 + 1] = rss[0];
    }
}

__global__ void k_mlp_final(const float* __restrict__ gm, const float* __restrict__ bg,
                            float* __restrict__ out4) {
    int b = blockIdx.x >> 3, g = blockIdx.x & 7;
    int t = threadIdx.x;
    int o = g*128 + t;
    float S = 0.f, SS = 0.f;
    #pragma unroll
    for (int seg = 0; seg < 8; seg++) {
        S  += g_gp[((b*8 + g)*8 + seg)*2 + 0];
        SS += g_gp[((b*8 + g)*8 + seg)*2 + 1];
    }
    float mx = -FLT_MAX, mn = FLT_MAX;
    #pragma unroll
    for (int seg = 0; seg < 8; seg++) {
        mx = fmaxf(mx, g_mmax[(b*8 + seg)*MLPO + o]);
        mn = fminf(mn, g_mmin[(b*8 + seg)*MLPO + o]);
    }
    float invc = 1.f / ((float)NPTS * 128.f);
    float mean = S * invc;
    float var  = SS * invc - mean*mean;
    float r = rsqrtf(var + EPSV);
    float sg = gm[o] * r;
    float tt = bg[o] - sg * mean;
    float h = (sg >= 0.f) ? mx : mn;
    float v = sg*h + tt;
    out4[b*MLPO + o] = fmaxf(v, 0.f);
}

// ---------------- feats transpose -> x_features [B,256,N] ----------------
__global__ void k_featsT(float* __restrict__ outf) {
    __shared__ float tile[32][33];
    int c0 = blockIdx.x * 32, n0 = blockIdx.y * 32, b = blockIdx.z;
    for (int i = threadIdx.y; i < 32; i += 8)
        tile[i][threadIdx.x] = g_feats[((size_t)(b*NPTS + n0 + i))*FEAT + c0 + threadIdx.x];
    __syncthreads();
    for (int i = threadIdx.y; i < 32; i += 8)
        outf[((size_t)b*FEAT + c0 + i)*NPTS + n0 + threadIdx.x] = tile[threadIdx.x][i];
}

// ---------------- launch ----------------
extern "C" void kernel_launch(void* const* d_in, const int* in_sizes, int n_in,
                              void* d_out, int out_size) {
    const float* x  = (const float*)d_in[0];
    const float* W1 = (const float*)d_in[1];
    const float* g1 = (const float*)d_in[2];
    const float* b1 = (const float*)d_in[3];
    const float* W2 = (const float*)d_in[4];
    const float* g2 = (const float*)d_in[5];
    const float* b2 = (const float*)d_in[6];
    const float* W3 = (const float*)d_in[7];
    const float* g3 = (const float*)d_in[8];
    const float* b3 = (const float*)d_in[9];
    const float* Wm = (const float*)d_in[10];
    const float* bm = (const float*)d_in[11];
    const float* gm = (const float*)d_in[12];
    const float* bg = (const float*)d_in[13];
    float* out = (float*)d_out;

    // launch 3 (ncu window) = k_knn_g
    k_transpose<<<96, 256>>>(x);
    k_wt<<<32, 256>>>(W1, W2, W3);

    // Layer 1: C=3 -> O=64, G=2
    k_keys3<<<dim3(NPTS/8, BATCH), 256>>>();
    k_knn_g<<<BATCH*NPTS/8, 256>>>();
    k_prep<<<BATCH*NPTS/16, 64>>>(0, 1, 0, 3, 64);
    k_edge<<<BATCH*NPTS/4, 128>>>(64);
    k_gnstats<<<BATCH*2, 256>>>(2, 64, g1, b1);
    k_edge_final<<<BATCH*NPTS*64/256, 256>>>(64, 0);

    // Layer 2: C=64 (x1) -> O=64, G=2
    k_sq<<<BATCH*NPTS/8, 256>>>(0);
    k_key_gemm_tc<<<dim3(16,16,BATCH), 256>>>(0);
    k_knn_g<<<BATCH*NPTS/8, 256>>>();
    k_prep<<<BATCH*NPTS/16, 64>>>(1, 0, 0, 64, 64);
    k_edge<<<BATCH*NPTS/4, 128>>>(64);
    k_gnstats<<<BATCH*2, 256>>>(2, 64, g2, b2);
    k_edge_final<<<BATCH*NPTS*64/256, 256>>>(64, 64);

    // Layer 3: C=64 (x2) -> O=128, G=4
    k_sq<<<BATCH*NPTS/8, 256>>>(64);
    k_key_gemm_tc<<<dim3(16,16,BATCH), 256>>>(64);
    k_knn_g<<<BATCH*NPTS/8, 256>>>();
    k_prep<<<BATCH*NPTS/16, 128>>>(2, 0, 64, 64, 128);
    k_edge<<<BATCH*NPTS/2, 128>>>(128);
    k_gnstats<<<BATCH*4, 256>>>(4, 128, g3, b3);
    k_edge_final<<<BATCH*NPTS*128/256, 256>>>(128, 128);

    // MLP head (Wm pre-split just before use)
    k_wsplit<<<MLPO*FEAT/256, 256>>>(Wm);
    k_mlp_gemm_tc<<<dim3(MLPO/128, BATCH*NPTS/128), 256>>>(bm);
    k_mlp_part<<<dim3(8, 8, BATCH), 128>>>();
    k_mlp_final<<<BATCH*8, 128>>>(gm, bg, out);

    // x_features output
    k_featsT<<<dim3(FEAT/32, NPTS/32, BATCH), dim3(32, 8)>>>(out + BATCH*MLPO);
}

// round 14
// speedup vs baseline: 1.1171x; 1.1171x over previous
#include <cuda_runtime.h>
#include <float.h>
#include <math.h>

#define BATCH 4
#define NPTS  2048
#define KNN   80
#define FEAT  256
#define MLPO  1024
#define EPSV  1e-5f
#define KPAD  36         // smem row stride for GEMM tiles (bank-conflict-free)
#define CAP   256        // per-warp candidate list capacity (fallback beyond)

// ---------------- scratch (static device globals; no allocation) ----------------
__device__ float    g_xt[BATCH*NPTS*3];
__device__ __align__(16) unsigned g_key[(size_t)BATCH*NPTS*NPTS];  // 64 MB key scratch
__device__ int      g_idx[BATCH*NPTS*KNN];
__device__ float    g_sq[BATCH*NPTS];
__device__ __align__(16) float g_y[BATCH*NPTS*128];
__device__ __align__(16) float g_c[BATCH*NPTS*128];
__device__ __align__(16) float g_hmax[BATCH*NPTS*128];
__device__ __align__(16) float g_hmin[BATCH*NPTS*128];
__device__ float    g_pst[BATCH*NPTS*4*2];
__device__ float    g_ss[BATCH*MLPO*2];
__device__ float    g_feats[BATCH*NPTS*FEAT];
__device__ float    g_h[(size_t)BATCH*NPTS*MLPO];
__device__ float    g_mmax[BATCH*8*MLPO];
__device__ float    g_mmin[BATCH*8*MLPO];
__device__ float    g_gp[BATCH*8*8*2];
__device__ float    g_wlt[3][64*128];                 // transposed Wl  [c][o]
__device__ float    g_wdt[3][64*128];                 // transposed Wr-Wl [c][o]

// ---------------- helpers ----------------
__device__ __forceinline__ unsigned f2u(float f) {
    unsigned u = __float_as_uint(f);
    return (u & 0x80000000u) ? ~u : (u | 0x80000000u);
}

__device__ __forceinline__ void mma_tf32(float c[4], unsigned a0, unsigned a1,
                                         unsigned a2, unsigned a3,
                                         unsigned b0, unsigned b1) {
    asm volatile(
        "mma.sync.aligned.m16n8k8.row.col.f32.tf32.tf32.f32 "
        "{%0,%1,%2,%3}, {%4,%5,%6,%7}, {%8,%9}, {%0,%1,%2,%3};\n"
        : "+f"(c[0]), "+f"(c[1]), "+f"(c[2]), "+f"(c[3])
        : "r"(a0), "r"(a1), "r"(a2), "r"(a3), "r"(b0), "r"(b1));
}

__device__ __forceinline__ void tf32split(float v, unsigned& hi, unsigned& lo) {
    unsigned h;
    asm("cvt.rna.tf32.f32 %0, %1;" : "=r"(h) : "f"(v));
    float hf = __uint_as_float(h);
    asm("cvt.rna.tf32.f32 %0, %1;" : "=r"(lo) : "f"(v - hf));
    hi = h;
}

__device__ __forceinline__ int warp_excl_scan(int v, int lane, int& tot) {
    int x = v;
    #pragma unroll
    for (int off = 1; off < 32; off <<= 1) {
        int t = __shfl_up_sync(0xFFFFFFFFu, x, off);
        if (lane >= off) x += t;
    }
    tot = __shfl_sync(0xFFFFFFFFu, x, 31);
    return x - v;
}

// ---------------- transpose x [B,3,N] -> xt [B,N,3] ----------------
__global__ void k_transpose(const float* __restrict__ x) {
    int i = blockIdx.x * 256 + threadIdx.x;
    if (i < BATCH*3*NPTS) {
        int b = i / (3*NPTS);
        int r = i % (3*NPTS);
        int c = r / NPTS, n = r % NPTS;
        g_xt[(b*NPTS + n)*3 + c] = x[i];
    }
}

// ---------------- weight transpose: W[o][2C] -> wlt[c][o], wdt[c][o] ----------------
__global__ void k_wt(const float* __restrict__ W1, const float* __restrict__ W2,
                     const float* __restrict__ W3) {
    int i = blockIdx.x * 256 + threadIdx.x;
    if (i < 3*64) {
        int c = i / 64, o = i % 64;
        float wl = W1[o*6 + c];
        g_wlt[0][c*64 + o] = wl;
        g_wdt[0][c*64 + o] = W1[o*6 + 3 + c] - wl;
    }
    if (i < 64*64) {
        int c = i / 64, o = i % 64;
        float wl = W2[o*128 + c];
        g_wlt[1][c*64 + o] = wl;
        g_wdt[1][c*64 + o] = W2[o*128 + 64 + c] - wl;
    }
    if (i < 64*128) {
        int c = i >> 7, o = i & 127;
        float wl = W3[o*128 + c];
        g_wlt[2][c*128 + o] = wl;
        g_wdt[2][c*128 + o] = W3[o*128 + 64 + c] - wl;
    }
}

// ---------------- layer-1 keys: g_key[b,n,m] = f2u(2*<x_n,x_m> - |x_m|^2) ----------
__global__ void __launch_bounds__(256) k_keys3() {
    __shared__ float sx[NPTS], sy[NPTS], sz[NPTS], sq[NPTS];
    int b = blockIdx.y;
    int n0 = blockIdx.x * 8;
    int tid = threadIdx.x;
    const float* base = &g_xt[(b*NPTS)*3];
    for (int i = tid; i < NPTS; i += 256) {
        float X = base[i*3], Y = base[i*3+1], Z = base[i*3+2];
        sx[i] = X; sy[i] = Y; sz[i] = Z;
        sq[i] = X*X + Y*Y + Z*Z;
    }
    __syncthreads();
    #pragma unroll
    for (int r = 0; r < 8; r++) {
        int n = n0 + r;
        float cx = sx[n], cy = sy[n], cz = sz[n];
        unsigned* row = &g_key[((size_t)(b*NPTS + n))*NPTS];
        for (int m = tid; m < NPTS; m += 256) {
            float key = 2.f*(cx*sx[m] + cy*sy[m] + cz*sz[m]) - sq[m];
            row[m] = f2u(key);
        }
    }
}

// ---------------- squared norms of feature rows ----------------
__global__ void k_sq(int foff) {
    int p = blockIdx.x * 8 + (threadIdx.x >> 5);
    int lane = threadIdx.x & 31;
    if (p < BATCH*NPTS) {
        const float* r = &g_feats[(size_t)p*FEAT + foff];
        float v = r[lane], w = r[lane + 32];
        float s = v*v + w*w;
        #pragma unroll
        for (int o = 16; o; o >>= 1) s += __shfl_xor_sync(~0u, s, o);
        if (lane == 0) g_sq[p] = s;
    }
}

// ---------------- warp top-80 radix select over a GLOBAL key row (3-scan) ----------
// Passes 1-2 resolve the top-16-bit prefix. Scan 3 emits all keys with top16 >
// prefix (order-free; downstream set-invariant) and compacts top16 == prefix
// candidates as (low16 << 16) | (2047 - idx). Exact rank over the small list
// reproduces jax.lax.top_k semantics. Scan 3 uses ONE packed warp-scan per
// quad (counts <=4, totals <=128: cg in low half, ce in high half; no carry).
__device__ __forceinline__ void warp_topk80_g(const uint4* __restrict__ sk4,
                                              int* __restrict__ hist,
                                              unsigned* __restrict__ cand, int p) {
    const unsigned FULL = 0xFFFFFFFFu;
    int lane = threadIdx.x & 31;
    unsigned prefix = 0, maskacc = 0;
    int kneed = KNN;
    #pragma unroll
    for (int pass = 0; pass < 2; pass++) {
        int shift = 24 - 8*pass;
        #pragma unroll
        for (int i = 0; i < 8; i++) hist[lane*8 + i] = 0;
        __syncwarp();
        #pragma unroll 4
        for (int v = 0; v < 16; v++) {
            uint4 q = sk4[(v << 5) + lane];
            if ((q.x & maskacc) == prefix) atomicAdd(&hist[(q.x >> shift) & 255], 1);
            if ((q.y & maskacc) == prefix) atomicAdd(&hist[(q.y >> shift) & 255], 1);
            if ((q.z & maskacc) == prefix) atomicAdd(&hist[(q.z >> shift) & 255], 1);
            if ((q.w & maskacc) == prefix) atomicAdd(&hist[(q.w >> shift) & 255], 1);
        }
        __syncwarp();
        int h[8], lsum = 0;
        #pragma unroll
        for (int i = 0; i < 8; i++) { h[i] = hist[lane*8 + i]; lsum += h[i]; }
        int v = lsum;
        #pragma unroll
        for (int off = 1; off < 32; off <<= 1) {
            int t = __shfl_down_sync(FULL, v, off);
            if (lane < 32 - off) v += t;
        }
        int run = v - lsum;
        int selbyte = -1, selrem = 0;
        #pragma unroll
        for (int i = 7; i >= 0; i--) {
            int incl = run + h[i];
            if (run < kneed && kneed <= incl) { selbyte = lane*8 + i; selrem = kneed - run; }
            run = incl;
        }
        unsigned ball = __ballot_sync(FULL, selbyte >= 0);
        int srcl = __ffs(ball) - 1;
        selbyte = __shfl_sync(FULL, selbyte, srcl);
        selrem  = __shfl_sync(FULL, selrem,  srcl);
        prefix |= ((unsigned)selbyte) << shift;
        maskacc |= (0xFFu << shift);
        kneed = selrem;
        __syncwarp();
    }
    unsigned pref16 = prefix >> 16;
    int* out = &g_idx[p*KNN];
    int totG = KNN - kneed;
    int baseG = 0, nl = 0;
    #pragma unroll 1
    for (int v = 0; v < 16; v++) {
        uint4 q = sk4[(v << 5) + lane];
        int i0 = ((v << 5) + lane) << 2;
        unsigned h0 = q.x >> 16, h1 = q.y >> 16, h2 = q.z >> 16, h3 = q.w >> 16;
        int cg = (h0 > pref16) + (h1 > pref16) + (h2 > pref16) + (h3 > pref16);
        int ce = (h0 == pref16) + (h1 == pref16) + (h2 == pref16) + (h3 == pref16);
        int tot;
        int pre = warp_excl_scan(cg | (ce << 16), lane, tot);
        int totg = tot & 0xFFFF, tote = tot >> 16;
        if (totg) {
            int off = baseG + (pre & 0xFFFF);
            if (h0 > pref16) out[off++] = i0;
            if (h1 > pref16) out[off++] = i0 + 1;
            if (h2 > pref16) out[off++] = i0 + 2;
            if (h3 > pref16) out[off++] = i0 + 3;
        }
        if (tote) {
            int pos = nl + (pre >> 16);
            if (h0 == pref16) { if (pos < CAP) cand[pos] = ((q.x & 0xFFFFu) << 16) | (unsigned)(2047 - i0);     pos++; }
            if (h1 == pref16) { if (pos < CAP) cand[pos] = ((q.y & 0xFFFFu) << 16) | (unsigned)(2047 - (i0+1)); pos++; }
            if (h2 == pref16) { if (pos < CAP) cand[pos] = ((q.z & 0xFFFFu) << 16) | (unsigned)(2047 - (i0+2)); pos++; }
            if (h3 == pref16) { if (pos < CAP) cand[pos] = ((q.w & 0xFFFFu) << 16) | (unsigned)(2047 - (i0+3)); pos++; }
        }
        baseG += totg;
        nl += tote;
    }
    __syncwarp();
    if (nl <= CAP) {
        for (int i = lane; i < nl; i += 32) {
            unsigned mine = cand[i];
            int rank = 0;
            for (int j = 0; j < nl; j++) rank += (cand[j] > mine);
            if (rank < kneed) out[totG + rank] = 2047 - (int)(mine & 0xFFFFu);
        }
    } else {
        // fallback: full-row passes at shift 8, 0, then full emission (proven path)
        #pragma unroll
        for (int pass = 0; pass < 2; pass++) {
            int shift = 8 - 8*pass;
            #pragma unroll
            for (int i = 0; i < 8; i++) hist[lane*8 + i] = 0;
            __syncwarp();
            #pragma unroll 4
            for (int v = 0; v < 16; v++) {
                uint4 q = sk4[(v << 5) + lane];
                if ((q.x & maskacc) == prefix) atomicAdd(&hist[(q.x >> shift) & 255], 1);
                if ((q.y & maskacc) == prefix) atomicAdd(&hist[(q.y >> shift) & 255], 1);
                if ((q.z & maskacc) == prefix) atomicAdd(&hist[(q.z >> shift) & 255], 1);
                if ((q.w & maskacc) == prefix) atomicAdd(&hist[(q.w >> shift) & 255], 1);
            }
            __syncwarp();
            int h[8], lsum = 0;
            #pragma unroll
            for (int i = 0; i < 8; i++) { h[i] = hist[lane*8 + i]; lsum += h[i]; }
            int v = lsum;
            #pragma unroll
            for (int off = 1; off < 32; off <<= 1) {
                int t = __shfl_down_sync(FULL, v, off);
                if (lane < 32 - off) v += t;
            }
            int run = v - lsum;
            int selbyte = -1, selrem = 0;
            #pragma unroll
            for (int i = 7; i >= 0; i--) {
                int incl = run + h[i];
                if (run < kneed && kneed <= incl) { selbyte = lane*8 + i; selrem = kneed - run; }
                run = incl;
            }
            unsigned ball = __ballot_sync(FULL, selbyte >= 0);
            int srcl = __ffs(ball) - 1;
            selbyte = __shfl_sync(FULL, selbyte, srcl);
            selrem  = __shfl_sync(FULL, selrem,  srcl);
            prefix |= ((unsigned)selbyte) << shift;
            maskacc |= (0xFFu << shift);
            kneed = selrem;
            __syncwarp();
        }
        unsigned T = prefix;
        int totG2 = KNN - kneed;
        int bG = 0, bE = 0;
        #pragma unroll 1
        for (int v = 0; v < 16; v++) {
            uint4 q = sk4[(v << 5) + lane];
            int i0 = ((v << 5) + lane) << 2;
            int cg = (q.x > T) + (q.y > T) + (q.z > T) + (q.w > T);
            int ce = (q.x == T) + (q.y == T) + (q.z == T) + (q.w == T);
            int tot;
            int pre = warp_excl_scan(cg | (ce << 16), lane, tot);
            int totg = tot & 0xFFFF, tote = tot >> 16;
            if (totg) {
                int off = bG + (pre & 0xFFFF);
                if (q.x > T) out[off++] = i0;
                if (q.y > T) out[off++] = i0 + 1;
                if (q.z > T) out[off++] = i0 + 2;
                if (q.w > T) out[off++] = i0 + 3;
            }
            if (tote) {
                int pos = bE + (pre >> 16);
                if (q.x == T) { if (pos < kneed) out[totG2 + pos] = i0;     pos++; }
                if (q.y == T) { if (pos < kneed) out[totG2 + pos] = i0 + 1; pos++; }
                if (q.z == T) { if (pos < kneed) out[totG2 + pos] = i0 + 2; pos++; }
                if (q.w == T) { if (pos < kneed) out[totG2 + pos] = i0 + 3; pos++; }
            }
            bG += totg;
            bE += tote;
        }
    }
}

// ---------------- kNN (all layers): 8 warps/block, keys from g_key ----------------
__global__ void __launch_bounds__(256) k_knn_g() {
    __shared__ int      shist[8][256];   // 8 KB
    __shared__ unsigned scand[8][CAP];   // 8 KB
    int w = threadIdx.x >> 5;
    int p = blockIdx.x * 8 + w;          // b*N + n
    const uint4* row4 = (const uint4*)&g_key[(size_t)p*NPTS];
    warp_topk80_g(row4, shist[w], scand[w], p);
}

// ---------------- key GEMM (tensor core, 3xTF32): keys = f2u(2*A.B^T - sq[m]) -----
__global__ void __launch_bounds__(256) k_key_gemm_tc(int foff) {
    __shared__ float As[128*KPAD];
    __shared__ float Bs[128*KPAD];
    int b = blockIdx.z;
    int row0 = blockIdx.y * 128, col0 = blockIdx.x * 128;
    int tid = threadIdx.x;
    int wid = tid >> 5, lane = tid & 31;
    int wm = wid >> 2, wn = wid & 3;
    int gid = lane >> 2, tig = lane & 3;
    float acc[4][4][4];
    #pragma unroll
    for (int mt = 0; mt < 4; mt++)
        #pragma unroll
        for (int nt = 0; nt < 4; nt++)
            #pragma unroll
            for (int q = 0; q < 4; q++) acc[mt][nt][q] = 0.f;

    for (int ch = 0; ch < 2; ch++) {
        const float* Ag = &g_feats[(size_t)(b*NPTS + row0)*FEAT + foff + ch*32];
        const float* Bg = &g_feats[(size_t)(b*NPTS + col0)*FEAT + foff + ch*32];
        #pragma unroll
        for (int i = 0; i < 4; i++) {
            int idx = tid + 256*i;
            int r = idx >> 3, c = (idx & 7) << 2;
            *(float4*)&As[r*KPAD + c] = *(const float4*)(Ag + (size_t)r*FEAT + c);
            *(float4*)&Bs[r*KPAD + c] = *(const float4*)(Bg + (size_t)r*FEAT + c);
        }
        __syncthreads();
        #pragma unroll
        for (int ks = 0; ks < 4; ks++) {
            int k0 = ks*8;
            unsigned bhi[4][2], blo[4][2];
            #pragma unroll
            for (int nt = 0; nt < 4; nt++) {
                int rB = (wn*32 + nt*8 + gid)*KPAD + k0 + tig;
                tf32split(Bs[rB],     bhi[nt][0], blo[nt][0]);
                tf32split(Bs[rB + 4], bhi[nt][1], blo[nt][1]);
            }
            #pragma unroll
            for (int mt = 0; mt < 4; mt++) {
                int rA = (wm*64 + mt*16 + gid)*KPAD + k0 + tig;
                unsigned ah[4], al[4];
                tf32split(As[rA],              ah[0], al[0]);
                tf32split(As[rA + 8*KPAD],     ah[1], al[1]);
                tf32split(As[rA + 4],          ah[2], al[2]);
                tf32split(As[rA + 8*KPAD + 4], ah[3], al[3]);
                #pragma unroll
                for (int nt = 0; nt < 4; nt++) {
                    mma_tf32(acc[mt][nt], ah[0], ah[1], ah[2], ah[3], bhi[nt][0], bhi[nt][1]);
                    mma_tf32(acc[mt][nt], ah[0], ah[1], ah[2], ah[3], blo[nt][0], blo[nt][1]);
                    mma_tf32(acc[mt][nt], al[0], al[1], al[2], al[3], bhi[nt][0], bhi[nt][1]);
                }
            }
        }
        __syncthreads();
    }
    const float* sqb = &g_sq[b*NPTS];
    unsigned* keyb = &g_key[(size_t)b*NPTS*NPTS];
    #pragma unroll
    for (int mt = 0; mt < 4; mt++) {
        int rg = row0 + wm*64 + mt*16 + gid;
        #pragma unroll
        for (int nt = 0; nt < 4; nt++) {
            int cg = col0 + wn*32 + nt*8 + tig*2;
            float s0 = sqb[cg], s1 = sqb[cg+1];
            uint2 v0 = make_uint2(f2u(2.f*acc[mt][nt][0] - s0),
                                  f2u(2.f*acc[mt][nt][1] - s1));
            uint2 v1 = make_uint2(f2u(2.f*acc[mt][nt][2] - s0),
                                  f2u(2.f*acc[mt][nt][3] - s1));
            *(uint2*)&keyb[(size_t)rg*NPTS + cg] = v0;
            *(uint2*)&keyb[(size_t)(rg+8)*NPTS + cg] = v1;
        }
    }
}

// ---------------- MLP GEMM (tensor core, 3xTF32): h = feats @ Wm^T + bm -----------
__global__ void __launch_bounds__(256) k_mlp_gemm_tc(const float* __restrict__ Wm,
                                                     const float* __restrict__ bm) {
    __shared__ float As[128*KPAD];
    __shared__ float Bs[128*KPAD];
    int row0 = blockIdx.y * 128, col0 = blockIdx.x * 128;
    int tid = threadIdx.x;
    int wid = tid >> 5, lane = tid & 31;
    int wm = wid >> 2, wn = wid & 3;
    int gid = lane >> 2, tig = lane & 3;
    float acc[4][4][4];
    #pragma unroll
    for (int mt = 0; mt < 4; mt++)
        #pragma unroll
        for (int nt = 0; nt < 4; nt++)
            #pragma unroll
            for (int q = 0; q < 4; q++) acc[mt][nt][q] = 0.f;

    for (int ch = 0; ch < 8; ch++) {
        const float* Ag = &g_feats[(size_t)row0*FEAT + ch*32];
        const float* Bg = &Wm[(size_t)col0*FEAT + ch*32];
        #pragma unroll
        for (int i = 0; i < 4; i++) {
            int idx = tid + 256*i;
            int r = idx >> 3, c = (idx & 7) << 2;
            *(float4*)&As[r*KPAD + c] = *(const float4*)(Ag + (size_t)r*FEAT + c);
            *(float4*)&Bs[r*KPAD + c] = *(const float4*)(Bg + (size_t)r*FEAT + c);
        }
        __syncthreads();
        #pragma unroll
        for (int ks = 0; ks < 4; ks++) {
            int k0 = ks*8;
            unsigned bhi[4][2], blo[4][2];
            #pragma unroll
            for (int nt = 0; nt < 4; nt++) {
                int rB = (wn*32 + nt*8 + gid)*KPAD + k0 + tig;
                tf32split(Bs[rB],     bhi[nt][0], blo[nt][0]);
                tf32split(Bs[rB + 4], bhi[nt][1], blo[nt][1]);
            }
            #pragma unroll
            for (int mt = 0; mt < 4; mt++) {
                int rA = (wm*64 + mt*16 + gid)*KPAD + k0 + tig;
                unsigned ah[4], al[4];
                tf32split(As[rA],              ah[0], al[0]);
                tf32split(As[rA + 8*KPAD],     ah[1], al[1]);
                tf32split(As[rA + 4],          ah[2], al[2]);
                tf32split(As[rA + 8*KPAD + 4], ah[3], al[3]);
                #pragma unroll
                for (int nt = 0; nt < 4; nt++) {
                    mma_tf32(acc[mt][nt], ah[0], ah[1], ah[2], ah[3], bhi[nt][0], bhi[nt][1]);
                    mma_tf32(acc[mt][nt], ah[0], ah[1], ah[2], ah[3], blo[nt][0], blo[nt][1]);
                    mma_tf32(acc[mt][nt], al[0], al[1], al[2], al[3], bhi[nt][0], bhi[nt][1]);
                }
            }
        }
        __syncthreads();
    }
    #pragma unroll
    for (int mt = 0; mt < 4; mt++) {
        int rg = row0 + wm*64 + mt*16 + gid;
        #pragma unroll
        for (int nt = 0; nt < 4; nt++) {
            int cg = col0 + wn*32 + nt*8 + tig*2;
            float b0 = bm[cg], b1 = bm[cg+1];
            float2 v0 = make_float2(acc[mt][nt][0] + b0, acc[mt][nt][1] + b1);
            float2 v1 = make_float2(acc[mt][nt][2] + b0, acc[mt][nt][3] + b1);
            *(float2*)&g_h[(size_t)rg*MLPO + cg] = v0;
            *(float2*)&g_h[(size_t)(rg+8)*MLPO + cg] = v1;
        }
    }
}

// ---------------- prep: y = f@Wl^T, c = f@(Wr-Wl)^T  (transposed weights) ----------
__global__ void k_prep(int layer, int use_xt, int foff, int Cin, int O) {
    __shared__ float sf[16*64];
    int p0 = blockIdx.x * 16;
    int tid = threadIdx.x;
    for (int i = tid; i < 16*Cin; i += O) {
        int rr = i / Cin, cc = i % Cin;
        int p = p0 + rr;
        sf[rr*Cin + cc] = use_xt ? g_xt[p*3 + cc]
                                 : g_feats[(size_t)p*FEAT + foff + cc];
    }
    __syncthreads();
    float y[16], c2[16];
    #pragma unroll
    for (int r = 0; r < 16; r++) { y[r] = 0.f; c2[r] = 0.f; }
    const float* wl = &g_wlt[layer][tid];
    const float* wd = &g_wdt[layer][tid];
    for (int c = 0; c < Cin; c++) {
        float a = wl[c*O];
        float d = wd[c*O];
        #pragma unroll
        for (int r = 0; r < 16; r++) {
            float fv = sf[r*Cin + c];
            y[r]  += fv * a;
            c2[r] += fv * d;
        }
    }
    #pragma unroll
    for (int r = 0; r < 16; r++) {
        g_y[(size_t)(p0 + r)*O + tid] = y[r];
        g_c[(size_t)(p0 + r)*O + tid] = c2[r];
    }
}

// ---------------- edge pass (float2, warp-per-point) ----------------
__global__ void __launch_bounds__(128) k_edge(int O) {
    __shared__ int sidx[4][KNN];
    int tid = threadIdx.x, wid = tid >> 5, lane = tid & 31;
    int wpp = O >> 6;                      // warps per point
    int ppb = 4 / wpp;                     // points per block
    int p = blockIdx.x * ppb + wid / wpp;
    int wip = wid % wpp;
    for (int i = lane; i < KNN; i += 32)
        sidx[wid][i] = g_idx[p*KNN + i];
    __syncwarp();
    int b = p >> 11;
    int ch = wip*64 + 2*lane;
    int halfO = O >> 1;
    const float2* ybase = (const float2*)&g_y[((size_t)b*NPTS)*O];
    float2 c = *(const float2*)&g_c[(size_t)p*O + ch];
    const int* si = sidx[wid];
    float mx0 = -FLT_MAX, mx1 = -FLT_MAX, mn0 = FLT_MAX, mn1 = FLT_MAX;
    float s = 0.f, ss = 0.f;
    int co = ch >> 1;
    #pragma unroll 4
    for (int k = 0; k < KNN; k++) {
        int j = si[k];
        float2 v = ybase[(size_t)j*halfO + co];
        float v0 = v.x + c.x, v1 = v.y + c.y;
        mx0 = fmaxf(mx0, v0); mn0 = fminf(mn0, v0);
        mx1 = fmaxf(mx1, v1); mn1 = fminf(mn1, v1);
        s += v0 + v1;
        ss += v0*v0 + v1*v1;
    }
    #pragma unroll
    for (int o = 8; o; o >>= 1) {
        s  += __shfl_xor_sync(0xFFFFFFFFu, s,  o);
        ss += __shfl_xor_sync(0xFFFFFFFFu, ss, o);
    }
    int G = O >> 5;
    int g = wip*2 + (lane >> 4);
    if ((lane & 15) == 0) {
        g_pst[((size_t)p*G + g)*2 + 0] = s;
        g_pst[((size_t)p*G + g)*2 + 1] = ss;
    }
    *(float2*)&g_hmax[(size_t)p*O + ch] = make_float2(mx0, mx1);
    *(float2*)&g_hmin[(size_t)p*O + ch] = make_float2(mn0, mn1);
}

// ---------------- GN stats reduce ----------------
__global__ void k_gnstats(int G, int O, const float* __restrict__ gamma,
                          const float* __restrict__ beta) {
    int b = blockIdx.x / G, g = blockIdx.x % G;
    int tid = threadIdx.x;
    float s = 0.f, ss = 0.f;
    for (int n = tid; n < NPTS; n += 256) {
        size_t base = (((size_t)(b*NPTS + n))*G + g)*2;
        s += g_pst[base]; ss += g_pst[base + 1];
    }
    __shared__ float rs[256], rss[256];
    rs[tid] = s; rss[tid] = ss;
    __syncthreads();
    for (int off = 128; off; off >>= 1) {
        if (tid < off) { rs[tid] += rs[tid+off]; rss[tid] += rss[tid+off]; }
        __syncthreads();
    }
    float invc = 1.f / ((float)NPTS * (float)KNN * 32.f);
    float mean = rs[0] * invc;
    float var  = rss[0] * invc - mean*mean;
    float r = rsqrtf(var + EPSV);
    if (tid < 32) {
        int o = g*32 + tid;
        float sg = gamma[o] * r;
        float tt = beta[o] - sg * mean;
        g_ss[(b*O + o)*2 + 0] = sg;
        g_ss[(b*O + o)*2 + 1] = tt;
    }
}

// ---------------- finalize ----------------
__global__ void k_edge_final(int O, int off) {
    int i = blockIdx.x*256 + threadIdx.x;
    if (i < BATCH*NPTS*O) {
        int p = i / O, o = i % O;
        int b = p >> 11;
        float sg = g_ss[(b*O + o)*2], tt = g_ss[(b*O + o)*2 + 1];
        float h = (sg >= 0.f) ? g_hmax[i] : g_hmin[i];
        float v = sg*h + tt;
        v = (v > 0.f) ? v : 0.2f*v;
        g_feats[(size_t)p*FEAT + off + o] = v;
    }
}

// ---------------- MLP head partials ----------------
__global__ void k_mlp_part() {
    int b = blockIdx.z, g = blockIdx.y, seg = blockIdx.x;
    int t = threadIdx.x;
    float mx = -FLT_MAX, mn = FLT_MAX, s = 0.f, ss = 0.f;
    int o = g*128 + t;
    for (int n = seg*256; n < seg*256 + 256; n++) {
        float v = g_h[((size_t)(b*NPTS + n))*MLPO + o];
        mx = fmaxf(mx, v); mn = fminf(mn, v);
        s += v; ss += v*v;
    }
    g_mmax[(b*8 + seg)*MLPO + o] = mx;
    g_mmin[(b*8 + seg)*MLPO + o] = mn;
    __shared__ float rs[128], rss[128];
    rs[t] = s; rss[t] = ss;
    __syncthreads();
    for (int off = 64; off; off >>= 1) {
        if (t < off) { rs[t] += rs[t+off]; rss[t] += rss[t+off]; }
        __syncthreads();
    }
    if (t == 0) {
        g_gp[((b*8 + g)*8 + seg)*2 + 0] = rs[0];
        g_gp[((b*8 + g)*8 + seg)*2 + 1] = rss[0];
    }
}

__global__ void k_mlp_final(const float* __restrict__ gm, const float* __restrict__ bg,
                            float* __restrict__ out4) {
    int b = blockIdx.x >> 3, g = blockIdx.x & 7;
    int t = threadIdx.x;
    int o = g*128 + t;
    float S = 0.f, SS = 0.f;
    #pragma unroll
    for (int seg = 0; seg < 8; seg++) {
        S  += g_gp[((b*8 + g)*8 + seg)*2 + 0];
        SS += g_gp[((b*8 + g)*8 + seg)*2 + 1];
    }
    float mx = -FLT_MAX, mn = FLT_MAX;
    #pragma unroll
    for (int seg = 0; seg < 8; seg++) {
        mx = fmaxf(mx, g_mmax[(b*8 + seg)*MLPO + o]);
        mn = fminf(mn, g_mmin[(b*8 + seg)*MLPO + o]);
    }
    float invc = 1.f / ((float)NPTS * 128.f);
    float mean = S * invc;
    float var  = SS * invc - mean*mean;
    float r = rsqrtf(var + EPSV);
    float sg = gm[o] * r;
    float tt = bg[o] - sg * mean;
    float h = (sg >= 0.f) ? mx : mn;
    float v = sg*h + tt;
    out4[b*MLPO + o] = fmaxf(v, 0.f);
}

// ---------------- feats transpose -> x_features [B,256,N] ----------------
__global__ void k_featsT(float* __restrict__ outf) {
    __shared__ float tile[32][33];
    int c0 = blockIdx.x * 32, n0 = blockIdx.y * 32, b = blockIdx.z;
    for (int i = threadIdx.y; i < 32; i += 8)
        tile[i][threadIdx.x] = g_feats[((size_t)(b*NPTS + n0 + i))*FEAT + c0 + threadIdx.x];
    __syncthreads();
    for (int i = threadIdx.y; i < 32; i += 8)
        outf[((size_t)b*FEAT + c0 + i)*NPTS + n0 + threadIdx.x] = tile[threadIdx.x][i];
}

// ---------------- launch ----------------
extern "C" void kernel_launch(void* const* d_in, const int* in_sizes, int n_in,
                              void* d_out, int out_size) {
    const float* x  = (const float*)d_in[0];
    const float* W1 = (const float*)d_in[1];
    const float* g1 = (const float*)d_in[2];
    const float* b1 = (const float*)d_in[3];
    const float* W2 = (const float*)d_in[4];
    const float* g2 = (const float*)d_in[5];
    const float* b2 = (const float*)d_in[6];
    const float* W3 = (const float*)d_in[7];
    const float* g3 = (const float*)d_in[8];
    const float* b3 = (const float*)d_in[9];
    const float* Wm = (const float*)d_in[10];
    const float* bm = (const float*)d_in[11];
    const float* gm = (const float*)d_in[12];
    const float* bg = (const float*)d_in[13];
    float* out = (float*)d_out;

    // launch 3 (ncu window) = k_knn_g
    k_transpose<<<96, 256>>>(x);
    k_wt<<<32, 256>>>(W1, W2, W3);

    // Layer 1: C=3 -> O=64, G=2
    k_keys3<<<dim3(NPTS/8, BATCH), 256>>>();
    k_knn_g<<<BATCH*NPTS/8, 256>>>();
    k_prep<<<BATCH*NPTS/16, 64>>>(0, 1, 0, 3, 64);
    k_edge<<<BATCH*NPTS/4, 128>>>(64);
    k_gnstats<<<BATCH*2, 256>>>(2, 64, g1, b1);
    k_edge_final<<<BATCH*NPTS*64/256, 256>>>(64, 0);

    // Layer 2: C=64 (x1) -> O=64, G=2
    k_sq<<<BATCH*NPTS/8, 256>>>(0);
    k_key_gemm_tc<<<dim3(16,16,BATCH), 256>>>(0);
    k_knn_g<<<BATCH*NPTS/8, 256>>>();
    k_prep<<<BATCH*NPTS/16, 64>>>(1, 0, 0, 64, 64);
    k_edge<<<BATCH*NPTS/4, 128>>>(64);
    k_gnstats<<<BATCH*2, 256>>>(2, 64, g2, b2);
    k_edge_final<<<BATCH*NPTS*64/256, 256>>>(64, 64);

    // Layer 3: C=64 (x2) -> O=128, G=4
    k_sq<<<BATCH*NPTS/8, 256>>>(64);
    k_key_gemm_tc<<<dim3(16,16,BATCH), 256>>>(64);
    k_knn_g<<<BATCH*NPTS/8, 256>>>();
    k_prep<<<BATCH*NPTS/16, 128>>>(2, 0, 64, 64, 128);
    k_edge<<<BATCH*NPTS/2, 128>>>(128);
    k_gnstats<<<BATCH*4, 256>>>(4, 128, g3, b3);
    k_edge_final<<<BATCH*NPTS*128/256, 256>>>(128, 128);

    // MLP head
    k_mlp_gemm_tc<<<dim3(MLPO/128, BATCH*NPTS/128), 256>>>(Wm, bm);
    k_mlp_part<<<dim3(8, 8, BATCH), 128>>>();
    k_mlp_final<<<BATCH*8, 128>>>(gm, bg, out);

    // x_features output
    k_featsT<<<dim3(FEAT/32, NPTS/32, BATCH), dim3(32, 8)>>>(out + BATCH*MLPO);
}

// round 15
// speedup vs baseline: 1.1307x; 1.0121x over previous
#include <cuda_runtime.h>
#include <float.h>
#include <math.h>

#define BATCH 4
#define NPTS  2048
#define KNN   80
#define FEAT  256
#define MLPO  1024
#define EPSV  1e-5f
#define KPAD  36         // smem row stride for GEMM tiles (bank-conflict-free)
#define CAP   256        // per-warp candidate list capacity (fallback beyond)

// ---------------- scratch (static device globals; no allocation) ----------------
__device__ __align__(16) unsigned g_key[(size_t)BATCH*NPTS*NPTS];  // 64 MB key scratch
__device__ int      g_idx[BATCH*NPTS*KNN];
__device__ float    g_sq[BATCH*NPTS];
__device__ __align__(16) float g_y[BATCH*NPTS*128];
__device__ __align__(16) float g_c[BATCH*NPTS*128];
__device__ __align__(16) float g_hmax[BATCH*NPTS*128];
__device__ __align__(16) float g_hmin[BATCH*NPTS*128];
__device__ float    g_pst[BATCH*NPTS*4*2];
__device__ float    g_ss[BATCH*MLPO*2];
__device__ float    g_feats[BATCH*NPTS*FEAT];
__device__ float    g_h[(size_t)BATCH*NPTS*MLPO];
__device__ float    g_mmax[BATCH*8*MLPO];
__device__ float    g_mmin[BATCH*8*MLPO];
__device__ float    g_gp[BATCH*8*8*2];
__device__ float    g_wlt[3][64*128];                 // transposed Wl  [c][o]
__device__ float    g_wdt[3][64*128];                 // transposed Wr-Wl [c][o]

// ---------------- helpers ----------------
__device__ __forceinline__ unsigned f2u(float f) {
    unsigned u = __float_as_uint(f);
    return (u & 0x80000000u) ? ~u : (u | 0x80000000u);
}

__device__ __forceinline__ void mma_tf32(float c[4], unsigned a0, unsigned a1,
                                         unsigned a2, unsigned a3,
                                         unsigned b0, unsigned b1) {
    asm volatile(
        "mma.sync.aligned.m16n8k8.row.col.f32.tf32.tf32.f32 "
        "{%0,%1,%2,%3}, {%4,%5,%6,%7}, {%8,%9}, {%0,%1,%2,%3};\n"
        : "+f"(c[0]), "+f"(c[1]), "+f"(c[2]), "+f"(c[3])
        : "r"(a0), "r"(a1), "r"(a2), "r"(a3), "r"(b0), "r"(b1));
}

__device__ __forceinline__ void tf32split(float v, unsigned& hi, unsigned& lo) {
    unsigned h;
    asm("cvt.rna.tf32.f32 %0, %1;" : "=r"(h) : "f"(v));
    float hf = __uint_as_float(h);
    asm("cvt.rna.tf32.f32 %0, %1;" : "=r"(lo) : "f"(v - hf));
    hi = h;
}

__device__ __forceinline__ int warp_excl_scan(int v, int lane, int& tot) {
    int x = v;
    #pragma unroll
    for (int off = 1; off < 32; off <<= 1) {
        int t = __shfl_up_sync(0xFFFFFFFFu, x, off);
        if (lane >= off) x += t;
    }
    tot = __shfl_sync(0xFFFFFFFFu, x, 31);
    return x - v;
}

// ---------------- layer-1 keys (reads x directly) + fused weight transpose --------
__global__ void __launch_bounds__(256) k_keys3(const float* __restrict__ x,
                                               const float* __restrict__ W1,
                                               const float* __restrict__ W2,
                                               const float* __restrict__ W3) {
    int tid = threadIdx.x;
    if (blockIdx.x == NPTS/8) {                       // fused weight transpose
        if (blockIdx.y != 0) return;
        for (int i = tid; i < 64*128; i += 256) {
            if (i < 3*64) {
                int c = i / 64, o = i % 64;
                float wl = W1[o*6 + c];
                g_wlt[0][c*64 + o] = wl;
                g_wdt[0][c*64 + o] = W1[o*6 + 3 + c] - wl;
            }
            if (i < 64*64) {
                int c = i / 64, o = i % 64;
                float wl = W2[o*128 + c];
                g_wlt[1][c*64 + o] = wl;
                g_wdt[1][c*64 + o] = W2[o*128 + 64 + c] - wl;
            }
            {
                int c = i >> 7, o = i & 127;
                float wl = W3[o*128 + c];
                g_wlt[2][c*128 + o] = wl;
                g_wdt[2][c*128 + o] = W3[o*128 + 64 + c] - wl;
            }
        }
        return;
    }
    __shared__ float sx[NPTS], sy[NPTS], sz[NPTS], sq[NPTS];
    int b = blockIdx.y;
    int n0 = blockIdx.x * 8;
    const float* xb = &x[(size_t)b*3*NPTS];
    for (int i = tid; i < NPTS; i += 256) {
        float X = xb[i], Y = xb[NPTS + i], Z = xb[2*NPTS + i];
        sx[i] = X; sy[i] = Y; sz[i] = Z;
        sq[i] = X*X + Y*Y + Z*Z;
    }
    __syncthreads();
    #pragma unroll
    for (int r = 0; r < 8; r++) {
        int n = n0 + r;
        float cx = sx[n], cy = sy[n], cz = sz[n];
        unsigned* row = &g_key[((size_t)(b*NPTS + n))*NPTS];
        for (int m = tid; m < NPTS; m += 256) {
            float key = 2.f*(cx*sx[m] + cy*sy[m] + cz*sz[m]) - sq[m];
            row[m] = f2u(key);
        }
    }
}

// ---------------- warp top-80 radix select over a GLOBAL key row (3-scan) ----------
__device__ __forceinline__ void warp_topk80_g(const uint4* __restrict__ sk4,
                                              int* __restrict__ hist,
                                              unsigned* __restrict__ cand, int p) {
    const unsigned FULL = 0xFFFFFFFFu;
    int lane = threadIdx.x & 31;
    unsigned prefix = 0, maskacc = 0;
    int kneed = KNN;
    #pragma unroll
    for (int pass = 0; pass < 2; pass++) {
        int shift = 24 - 8*pass;
        #pragma unroll
        for (int i = 0; i < 8; i++) hist[lane*8 + i] = 0;
        __syncwarp();
        #pragma unroll 4
        for (int v = 0; v < 16; v++) {
            uint4 q = sk4[(v << 5) + lane];
            if ((q.x & maskacc) == prefix) atomicAdd(&hist[(q.x >> shift) & 255], 1);
            if ((q.y & maskacc) == prefix) atomicAdd(&hist[(q.y >> shift) & 255], 1);
            if ((q.z & maskacc) == prefix) atomicAdd(&hist[(q.z >> shift) & 255], 1);
            if ((q.w & maskacc) == prefix) atomicAdd(&hist[(q.w >> shift) & 255], 1);
        }
        __syncwarp();
        int h[8], lsum = 0;
        #pragma unroll
        for (int i = 0; i < 8; i++) { h[i] = hist[lane*8 + i]; lsum += h[i]; }
        int v = lsum;
        #pragma unroll
        for (int off = 1; off < 32; off <<= 1) {
            int t = __shfl_down_sync(FULL, v, off);
            if (lane < 32 - off) v += t;
        }
        int run = v - lsum;
        int selbyte = -1, selrem = 0;
        #pragma unroll
        for (int i = 7; i >= 0; i--) {
            int incl = run + h[i];
            if (run < kneed && kneed <= incl) { selbyte = lane*8 + i; selrem = kneed - run; }
            run = incl;
        }
        unsigned ball = __ballot_sync(FULL, selbyte >= 0);
        int srcl = __ffs(ball) - 1;
        selbyte = __shfl_sync(FULL, selbyte, srcl);
        selrem  = __shfl_sync(FULL, selrem,  srcl);
        prefix |= ((unsigned)selbyte) << shift;
        maskacc |= (0xFFu << shift);
        kneed = selrem;
        __syncwarp();
    }
    unsigned pref16 = prefix >> 16;
    int* out = &g_idx[p*KNN];
    int totG = KNN - kneed;
    int baseG = 0, nl = 0;
    #pragma unroll 1
    for (int v = 0; v < 16; v++) {
        uint4 q = sk4[(v << 5) + lane];
        int i0 = ((v << 5) + lane) << 2;
        unsigned h0 = q.x >> 16, h1 = q.y >> 16, h2 = q.z >> 16, h3 = q.w >> 16;
        int cg = (h0 > pref16) + (h1 > pref16) + (h2 > pref16) + (h3 > pref16);
        int ce = (h0 == pref16) + (h1 == pref16) + (h2 == pref16) + (h3 == pref16);
        int tot;
        int pre = warp_excl_scan(cg | (ce << 16), lane, tot);
        int totg = tot & 0xFFFF, tote = tot >> 16;
        if (totg) {
            int off = baseG + (pre & 0xFFFF);
            if (h0 > pref16) out[off++] = i0;
            if (h1 > pref16) out[off++] = i0 + 1;
            if (h2 > pref16) out[off++] = i0 + 2;
            if (h3 > pref16) out[off++] = i0 + 3;
        }
        if (tote) {
            int pos = nl + (pre >> 16);
            if (h0 == pref16) { if (pos < CAP) cand[pos] = ((q.x & 0xFFFFu) << 16) | (unsigned)(2047 - i0);     pos++; }
            if (h1 == pref16) { if (pos < CAP) cand[pos] = ((q.y & 0xFFFFu) << 16) | (unsigned)(2047 - (i0+1)); pos++; }
            if (h2 == pref16) { if (pos < CAP) cand[pos] = ((q.z & 0xFFFFu) << 16) | (unsigned)(2047 - (i0+2)); pos++; }
            if (h3 == pref16) { if (pos < CAP) cand[pos] = ((q.w & 0xFFFFu) << 16) | (unsigned)(2047 - (i0+3)); pos++; }
        }
        baseG += totg;
        nl += tote;
    }
    __syncwarp();
    if (nl <= CAP) {
        for (int i = lane; i < nl; i += 32) {
            unsigned mine = cand[i];
            int rank = 0;
            for (int j = 0; j < nl; j++) rank += (cand[j] > mine);
            if (rank < kneed) out[totG + rank] = 2047 - (int)(mine & 0xFFFFu);
        }
    } else {
        // fallback: full-row passes at shift 8, 0, then full emission (proven path)
        #pragma unroll
        for (int pass = 0; pass < 2; pass++) {
            int shift = 8 - 8*pass;
            #pragma unroll
            for (int i = 0; i < 8; i++) hist[lane*8 + i] = 0;
            __syncwarp();
            #pragma unroll 4
            for (int v = 0; v < 16; v++) {
                uint4 q = sk4[(v << 5) + lane];
                if ((q.x & maskacc) == prefix) atomicAdd(&hist[(q.x >> shift) & 255], 1);
                if ((q.y & maskacc) == prefix) atomicAdd(&hist[(q.y >> shift) & 255], 1);
                if ((q.z & maskacc) == prefix) atomicAdd(&hist[(q.z >> shift) & 255], 1);
                if ((q.w & maskacc) == prefix) atomicAdd(&hist[(q.w >> shift) & 255], 1);
            }
            __syncwarp();
            int h[8], lsum = 0;
            #pragma unroll
            for (int i = 0; i < 8; i++) { h[i] = hist[lane*8 + i]; lsum += h[i]; }
            int v = lsum;
            #pragma unroll
            for (int off = 1; off < 32; off <<= 1) {
                int t = __shfl_down_sync(FULL, v, off);
                if (lane < 32 - off) v += t;
            }
            int run = v - lsum;
            int selbyte = -1, selrem = 0;
            #pragma unroll
            for (int i = 7; i >= 0; i--) {
                int incl = run + h[i];
                if (run < kneed && kneed <= incl) { selbyte = lane*8 + i; selrem = kneed - run; }
                run = incl;
            }
            unsigned ball = __ballot_sync(FULL, selbyte >= 0);
            int srcl = __ffs(ball) - 1;
            selbyte = __shfl_sync(FULL, selbyte, srcl);
            selrem  = __shfl_sync(FULL, selrem,  srcl);
            prefix |= ((unsigned)selbyte) << shift;
            maskacc |= (0xFFu << shift);
            kneed = selrem;
            __syncwarp();
        }
        unsigned T = prefix;
        int totG2 = KNN - kneed;
        int bG = 0, bE = 0;
        #pragma unroll 1
        for (int v = 0; v < 16; v++) {
            uint4 q = sk4[(v << 5) + lane];
            int i0 = ((v << 5) + lane) << 2;
            int cg = (q.x > T) + (q.y > T) + (q.z > T) + (q.w > T);
            int ce = (q.x == T) + (q.y == T) + (q.z == T) + (q.w == T);
            int tot;
            int pre = warp_excl_scan(cg | (ce << 16), lane, tot);
            int totg = tot & 0xFFFF, tote = tot >> 16;
            if (totg) {
                int off = bG + (pre & 0xFFFF);
                if (q.x > T) out[off++] = i0;
                if (q.y > T) out[off++] = i0 + 1;
                if (q.z > T) out[off++] = i0 + 2;
                if (q.w > T) out[off++] = i0 + 3;
            }
            if (tote) {
                int pos = bE + (pre >> 16);
                if (q.x == T) { if (pos < kneed) out[totG2 + pos] = i0;     pos++; }
                if (q.y == T) { if (pos < kneed) out[totG2 + pos] = i0 + 1; pos++; }
                if (q.z == T) { if (pos < kneed) out[totG2 + pos] = i0 + 2; pos++; }
                if (q.w == T) { if (pos < kneed) out[totG2 + pos] = i0 + 3; pos++; }
            }
            bG += totg;
            bE += tote;
        }
    }
}

// ---------------- kNN (all layers): 8 warps/block, keys from g_key ----------------
__global__ void __launch_bounds__(256) k_knn_g() {
    __shared__ int      shist[8][256];   // 8 KB
    __shared__ unsigned scand[8][CAP];   // 8 KB
    int w = threadIdx.x >> 5;
    int p = blockIdx.x * 8 + w;          // b*N + n
    const uint4* row4 = (const uint4*)&g_key[(size_t)p*NPTS];
    warp_topk80_g(row4, shist[w], scand[w], p);
}

// ---------------- key GEMM (tensor core, 3xTF32): keys = f2u(2*A.B^T - sq[m]) -----
__global__ void __launch_bounds__(256) k_key_gemm_tc(int foff) {
    __shared__ float As[128*KPAD];
    __shared__ float Bs[128*KPAD];
    int b = blockIdx.z;
    int row0 = blockIdx.y * 128, col0 = blockIdx.x * 128;
    int tid = threadIdx.x;
    int wid = tid >> 5, lane = tid & 31;
    int wm = wid >> 2, wn = wid & 3;
    int gid = lane >> 2, tig = lane & 3;
    float acc[4][4][4];
    #pragma unroll
    for (int mt = 0; mt < 4; mt++)
        #pragma unroll
        for (int nt = 0; nt < 4; nt++)
            #pragma unroll
            for (int q = 0; q < 4; q++) acc[mt][nt][q] = 0.f;

    for (int ch = 0; ch < 2; ch++) {
        const float* Ag = &g_feats[(size_t)(b*NPTS + row0)*FEAT + foff + ch*32];
        const float* Bg = &g_feats[(size_t)(b*NPTS + col0)*FEAT + foff + ch*32];
        #pragma unroll
        for (int i = 0; i < 4; i++) {
            int idx = tid + 256*i;
            int r = idx >> 3, c = (idx & 7) << 2;
            *(float4*)&As[r*KPAD + c] = *(const float4*)(Ag + (size_t)r*FEAT + c);
            *(float4*)&Bs[r*KPAD + c] = *(const float4*)(Bg + (size_t)r*FEAT + c);
        }
        __syncthreads();
        #pragma unroll
        for (int ks = 0; ks < 4; ks++) {
            int k0 = ks*8;
            unsigned bhi[4][2], blo[4][2];
            #pragma unroll
            for (int nt = 0; nt < 4; nt++) {
                int rB = (wn*32 + nt*8 + gid)*KPAD + k0 + tig;
                tf32split(Bs[rB],     bhi[nt][0], blo[nt][0]);
                tf32split(Bs[rB + 4], bhi[nt][1], blo[nt][1]);
            }
            #pragma unroll
            for (int mt = 0; mt < 4; mt++) {
                int rA = (wm*64 + mt*16 + gid)*KPAD + k0 + tig;
                unsigned ah[4], al[4];
                tf32split(As[rA],              ah[0], al[0]);
                tf32split(As[rA + 8*KPAD],     ah[1], al[1]);
                tf32split(As[rA + 4],          ah[2], al[2]);
                tf32split(As[rA + 8*KPAD + 4], ah[3], al[3]);
                #pragma unroll
                for (int nt = 0; nt < 4; nt++) {
                    mma_tf32(acc[mt][nt], ah[0], ah[1], ah[2], ah[3], bhi[nt][0], bhi[nt][1]);
                    mma_tf32(acc[mt][nt], ah[0], ah[1], ah[2], ah[3], blo[nt][0], blo[nt][1]);
                    mma_tf32(acc[mt][nt], al[0], al[1], al[2], al[3], bhi[nt][0], bhi[nt][1]);
                }
            }
        }
        __syncthreads();
    }
    const float* sqb = &g_sq[b*NPTS];
    unsigned* keyb = &g_key[(size_t)b*NPTS*NPTS];
    #pragma unroll
    for (int mt = 0; mt < 4; mt++) {
        int rg = row0 + wm*64 + mt*16 + gid;
        #pragma unroll
        for (int nt = 0; nt < 4; nt++) {
            int cg = col0 + wn*32 + nt*8 + tig*2;
            float s0 = sqb[cg], s1 = sqb[cg+1];
            uint2 v0 = make_uint2(f2u(2.f*acc[mt][nt][0] - s0),
                                  f2u(2.f*acc[mt][nt][1] - s1));
            uint2 v1 = make_uint2(f2u(2.f*acc[mt][nt][2] - s0),
                                  f2u(2.f*acc[mt][nt][3] - s1));
            *(uint2*)&keyb[(size_t)rg*NPTS + cg] = v0;
            *(uint2*)&keyb[(size_t)(rg+8)*NPTS + cg] = v1;
        }
    }
}

// ---------------- MLP GEMM (tensor core, 3xTF32): h = feats @ Wm^T + bm -----------
__global__ void __launch_bounds__(256) k_mlp_gemm_tc(const float* __restrict__ Wm,
                                                     const float* __restrict__ bm) {
    __shared__ float As[128*KPAD];
    __shared__ float Bs[128*KPAD];
    int row0 = blockIdx.y * 128, col0 = blockIdx.x * 128;
    int tid = threadIdx.x;
    int wid = tid >> 5, lane = tid & 31;
    int wm = wid >> 2, wn = wid & 3;
    int gid = lane >> 2, tig = lane & 3;
    float acc[4][4][4];
    #pragma unroll
    for (int mt = 0; mt < 4; mt++)
        #pragma unroll
        for (int nt = 0; nt < 4; nt++)
            #pragma unroll
            for (int q = 0; q < 4; q++) acc[mt][nt][q] = 0.f;

    for (int ch = 0; ch < 8; ch++) {
        const float* Ag = &g_feats[(size_t)row0*FEAT + ch*32];
        const float* Bg = &Wm[(size_t)col0*FEAT + ch*32];
        #pragma unroll
        for (int i = 0; i < 4; i++) {
            int idx = tid + 256*i;
            int r = idx >> 3, c = (idx & 7) << 2;
            *(float4*)&As[r*KPAD + c] = *(const float4*)(Ag + (size_t)r*FEAT + c);
            *(float4*)&Bs[r*KPAD + c] = *(const float4*)(Bg + (size_t)r*FEAT + c);
        }
        __syncthreads();
        #pragma unroll
        for (int ks = 0; ks < 4; ks++) {
            int k0 = ks*8;
            unsigned bhi[4][2], blo[4][2];
            #pragma unroll
            for (int nt = 0; nt < 4; nt++) {
                int rB = (wn*32 + nt*8 + gid)*KPAD + k0 + tig;
                tf32split(Bs[rB],     bhi[nt][0], blo[nt][0]);
                tf32split(Bs[rB + 4], bhi[nt][1], blo[nt][1]);
            }
            #pragma unroll
            for (int mt = 0; mt < 4; mt++) {
                int rA = (wm*64 + mt*16 + gid)*KPAD + k0 + tig;
                unsigned ah[4], al[4];
                tf32split(As[rA],              ah[0], al[0]);
                tf32split(As[rA + 8*KPAD],     ah[1], al[1]);
                tf32split(As[rA + 4],          ah[2], al[2]);
                tf32split(As[rA + 8*KPAD + 4], ah[3], al[3]);
                #pragma unroll
                for (int nt = 0; nt < 4; nt++) {
                    mma_tf32(acc[mt][nt], ah[0], ah[1], ah[2], ah[3], bhi[nt][0], bhi[nt][1]);
                    mma_tf32(acc[mt][nt], ah[0], ah[1], ah[2], ah[3], blo[nt][0], blo[nt][1]);
                    mma_tf32(acc[mt][nt], al[0], al[1], al[2], al[3], bhi[nt][0], bhi[nt][1]);
                }
            }
        }
        __syncthreads();
    }
    #pragma unroll
    for (int mt = 0; mt < 4; mt++) {
        int rg = row0 + wm*64 + mt*16 + gid;
        #pragma unroll
        for (int nt = 0; nt < 4; nt++) {
            int cg = col0 + wn*32 + nt*8 + tig*2;
            float b0 = bm[cg], b1 = bm[cg+1];
            float2 v0 = make_float2(acc[mt][nt][0] + b0, acc[mt][nt][1] + b1);
            float2 v1 = make_float2(acc[mt][nt][2] + b0, acc[mt][nt][3] + b1);
            *(float2*)&g_h[(size_t)rg*MLPO + cg] = v0;
            *(float2*)&g_h[(size_t)(rg+8)*MLPO + cg] = v1;
        }
    }
}

// ---------------- prep: y = f@Wl^T, c = f@(Wr-Wl)^T  (transposed weights) ----------
__global__ void k_prep(int layer, int use_x, int foff, int Cin, int O,
                       const float* __restrict__ x) {
    __shared__ float sf[16*64];
    int p0 = blockIdx.x * 16;
    int tid = threadIdx.x;
    for (int i = tid; i < 16*Cin; i += O) {
        int rr = i / Cin, cc = i % Cin;
        int p = p0 + rr;
        if (use_x) {
            int b = p >> 11, n = p & 2047;
            sf[rr*Cin + cc] = x[(size_t)b*3*NPTS + cc*NPTS + n];
        } else {
            sf[rr*Cin + cc] = g_feats[(size_t)p*FEAT + foff + cc];
        }
    }
    __syncthreads();
    float y[16], c2[16];
    #pragma unroll
    for (int r = 0; r < 16; r++) { y[r] = 0.f; c2[r] = 0.f; }
    const float* wl = &g_wlt[layer][tid];
    const float* wd = &g_wdt[layer][tid];
    for (int c = 0; c < Cin; c++) {
        float a = wl[c*O];
        float d = wd[c*O];
        #pragma unroll
        for (int r = 0; r < 16; r++) {
            float fv = sf[r*Cin + c];
            y[r]  += fv * a;
            c2[r] += fv * d;
        }
    }
    #pragma unroll
    for (int r = 0; r < 16; r++) {
        g_y[(size_t)(p0 + r)*O + tid] = y[r];
        g_c[(size_t)(p0 + r)*O + tid] = c2[r];
    }
}

// ---------------- edge pass (float2, warp-per-point) ----------------
__global__ void __launch_bounds__(128) k_edge(int O) {
    __shared__ int sidx[4][KNN];
    int tid = threadIdx.x, wid = tid >> 5, lane = tid & 31;
    int wpp = O >> 6;                      // warps per point
    int ppb = 4 / wpp;                     // points per block
    int p = blockIdx.x * ppb + wid / wpp;
    int wip = wid % wpp;
    for (int i = lane; i < KNN; i += 32)
        sidx[wid][i] = g_idx[p*KNN + i];
    __syncwarp();
    int b = p >> 11;
    int ch = wip*64 + 2*lane;
    int halfO = O >> 1;
    const float2* ybase = (const float2*)&g_y[((size_t)b*NPTS)*O];
    float2 c = *(const float2*)&g_c[(size_t)p*O + ch];
    const int* si = sidx[wid];
    float mx0 = -FLT_MAX, mx1 = -FLT_MAX, mn0 = FLT_MAX, mn1 = FLT_MAX;
    float s = 0.f, ss = 0.f;
    int co = ch >> 1;
    #pragma unroll 4
    for (int k = 0; k < KNN; k++) {
        int j = si[k];
        float2 v = ybase[(size_t)j*halfO + co];
        float v0 = v.x + c.x, v1 = v.y + c.y;
        mx0 = fmaxf(mx0, v0); mn0 = fminf(mn0, v0);
        mx1 = fmaxf(mx1, v1); mn1 = fminf(mn1, v1);
        s += v0 + v1;
        ss += v0*v0 + v1*v1;
    }
    #pragma unroll
    for (int o = 8; o; o >>= 1) {
        s  += __shfl_xor_sync(0xFFFFFFFFu, s,  o);
        ss += __shfl_xor_sync(0xFFFFFFFFu, ss, o);
    }
    int G = O >> 5;
    int g = wip*2 + (lane >> 4);
    if ((lane & 15) == 0) {
        g_pst[((size_t)p*G + g)*2 + 0] = s;
        g_pst[((size_t)p*G + g)*2 + 1] = ss;
    }
    *(float2*)&g_hmax[(size_t)p*O + ch] = make_float2(mx0, mx1);
    *(float2*)&g_hmin[(size_t)p*O + ch] = make_float2(mn0, mn1);
}

// ---------------- GN stats reduce ----------------
__global__ void k_gnstats(int G, int O, const float* __restrict__ gamma,
                          const float* __restrict__ beta) {
    int b = blockIdx.x / G, g = blockIdx.x % G;
    int tid = threadIdx.x;
    float s = 0.f, ss = 0.f;
    for (int n = tid; n < NPTS; n += 256) {
        size_t base = (((size_t)(b*NPTS + n))*G + g)*2;
        s += g_pst[base]; ss += g_pst[base + 1];
    }
    __shared__ float rs[256], rss[256];
    rs[tid] = s; rss[tid] = ss;
    __syncthreads();
    for (int off = 128; off; off >>= 1) {
        if (tid < off) { rs[tid] += rs[tid+off]; rss[tid] += rss[tid+off]; }
        __syncthreads();
    }
    float invc = 1.f / ((float)NPTS * (float)KNN * 32.f);
    float mean = rs[0] * invc;
    float var  = rss[0] * invc - mean*mean;
    float r = rsqrtf(var + EPSV);
    if (tid < 32) {
        int o = g*32 + tid;
        float sg = gamma[o] * r;
        float tt = beta[o] - sg * mean;
        g_ss[(b*O + o)*2 + 0] = sg;
        g_ss[(b*O + o)*2 + 1] = tt;
    }
}

// ---------------- finalize: feats + (optionally) fused per-point sq ----------------
__global__ void k_edge_final(int O, int off, int wsq) {
    __shared__ float ws[8];
    int i = blockIdx.x*256 + threadIdx.x;
    int p = i / O, o = i % O;
    int b = p >> 11;
    float sg = g_ss[(b*O + o)*2], tt = g_ss[(b*O + o)*2 + 1];
    float h = (sg >= 0.f) ? g_hmax[i] : g_hmin[i];
    float v = sg*h + tt;
    v = (v > 0.f) ? v : 0.2f*v;
    g_feats[(size_t)p*FEAT + off + o] = v;
    if (wsq) {
        float s = v*v;
        #pragma unroll
        for (int d = 16; d; d >>= 1) s += __shfl_xor_sync(0xFFFFFFFFu, s, d);
        int wid = threadIdx.x >> 5;
        if ((threadIdx.x & 31) == 0) ws[wid] = s;
        __syncthreads();
        if (o == 0) {
            int w0 = threadIdx.x >> 5;        // first warp of this point
            int wpp = O >> 5;                 // warps per point
            float tot = 0.f;
            for (int j = 0; j < wpp; j++) tot += ws[w0 + j];
            g_sq[p] = tot;
        }
    }
}

// ---------------- MLP head partials ----------------
__global__ void k_mlp_part() {
    int b = blockIdx.z, g = blockIdx.y, seg = blockIdx.x;
    int t = threadIdx.x;
    float mx = -FLT_MAX, mn = FLT_MAX, s = 0.f, ss = 0.f;
    int o = g*128 + t;
    for (int n = seg*256; n < seg*256 + 256; n++) {
        float v = g_h[((size_t)(b*NPTS + n))*MLPO + o];
        mx = fmaxf(mx, v); mn = fminf(mn, v);
        s += v; ss += v*v;
    }
    g_mmax[(b*8 + seg)*MLPO + o] = mx;
    g_mmin[(b*8 + seg)*MLPO + o] = mn;
    __shared__ float rs[128], rss[128];
    rs[t] = s; rss[t] = ss;
    __syncthreads();
    for (int off = 64; off; off >>= 1) {
        if (t < off) { rs[t] += rs[t+off]; rss[t] += rss[t+off]; }
        __syncthreads();
    }
    if (t == 0) {
        g_gp[((b*8 + g)*8 + seg)*2 + 0] = rs[0];
        g_gp[((b*8 + g)*8 + seg)*2 + 1] = rss[0];
    }
}

__global__ void k_mlp_final(const float* __restrict__ gm, const float* __restrict__ bg,
                            float* __restrict__ out4) {
    int b = blockIdx.x >> 3, g = blockIdx.x & 7;
    int t = threadIdx.x;
    int o = g*128 + t;
    float S = 0.f, SS = 0.f;
    #pragma unroll
    for (int seg = 0; seg < 8; seg++) {
        S  += g_gp[((b*8 + g)*8 + seg)*2 + 0];
        SS += g_gp[((b*8 + g)*8 + seg)*2 + 1];
    }
    float mx = -FLT_MAX, mn = FLT_MAX;
    #pragma unroll
    for (int seg = 0; seg < 8; seg++) {
        mx = fmaxf(mx, g_mmax[(b*8 + seg)*MLPO + o]);
        mn = fminf(mn, g_mmin[(b*8 + seg)*MLPO + o]);
    }
    float invc = 1.f / ((float)NPTS * 128.f);
    float mean = S * invc;
    float var  = SS * invc - mean*mean;
    float r = rsqrtf(var + EPSV);
    float sg = gm[o] * r;
    float tt = bg[o] - sg * mean;
    float h = (sg >= 0.f) ? mx : mn;
    float v = sg*h + tt;
    out4[b*MLPO + o] = fmaxf(v, 0.f);
}

// ---------------- feats transpose -> x_features [B,256,N] ----------------
__global__ void k_featsT(float* __restrict__ outf) {
    __shared__ float tile[32][33];
    int c0 = blockIdx.x * 32, n0 = blockIdx.y * 32, b = blockIdx.z;
    for (int i = threadIdx.y; i < 32; i += 8)
        tile[i][threadIdx.x] = g_feats[((size_t)(b*NPTS + n0 + i))*FEAT + c0 + threadIdx.x];
    __syncthreads();
    for (int i = threadIdx.y; i < 32; i += 8)
        outf[((size_t)b*FEAT + c0 + i)*NPTS + n0 + threadIdx.x] = tile[threadIdx.x][i];
}

// ---------------- launch ----------------
extern "C" void kernel_launch(void* const* d_in, const int* in_sizes, int n_in,
                              void* d_out, int out_size) {
    const float* x  = (const float*)d_in[0];
    const float* W1 = (const float*)d_in[1];
    const float* g1 = (const float*)d_in[2];
    const float* b1 = (const float*)d_in[3];
    const float* W2 = (const float*)d_in[4];
    const float* g2 = (const float*)d_in[5];
    const float* b2 = (const float*)d_in[6];
    const float* W3 = (const float*)d_in[7];
    const float* g3 = (const float*)d_in[8];
    const float* b3 = (const float*)d_in[9];
    const float* Wm = (const float*)d_in[10];
    const float* bm = (const float*)d_in[11];
    const float* gm = (const float*)d_in[12];
    const float* bg = (const float*)d_in[13];
    float* out = (float*)d_out;

    static cudaStream_t s2 = nullptr;
    static cudaEvent_t ef = nullptr, ej = nullptr;
    if (!s2) {
        cudaStreamCreateWithFlags(&s2, cudaStreamNonBlocking);
        cudaEventCreateWithFlags(&ef, cudaEventDisableTiming);
        cudaEventCreateWithFlags(&ej, cudaEventDisableTiming);
    }

    // Layer 1: keys (reads x directly) + fused weight transpose
    k_keys3<<<dim3(NPTS/8 + 1, BATCH), 256>>>(x, W1, W2, W3);
    // fork: prep1 (needs x + g_wlt from keys3) overlaps with knn
    cudaEventRecord(ef, 0);
    cudaStreamWaitEvent(s2, ef, 0);
    k_prep<<<BATCH*NPTS/16, 64, 0, s2>>>(0, 1, 0, 3, 64, x);
    cudaEventRecord(ej, s2);
    k_knn_g<<<BATCH*NPTS/8, 256>>>();
    cudaStreamWaitEvent(0, ej, 0);
    k_edge<<<BATCH*NPTS/4, 128>>>(64);
    k_gnstats<<<BATCH*2, 256>>>(2, 64, g1, b1);
    k_edge_final<<<BATCH*NPTS*64/256, 256>>>(64, 0, 1);

    // Layer 2
    k_key_gemm_tc<<<dim3(16,16,BATCH), 256>>>(0);
    cudaEventRecord(ef, 0);
    cudaStreamWaitEvent(s2, ef, 0);
    k_prep<<<BATCH*NPTS/16, 64, 0, s2>>>(1, 0, 0, 64, 64, x);
    cudaEventRecord(ej, s2);
    k_knn_g<<<BATCH*NPTS/8, 256>>>();
    cudaStreamWaitEvent(0, ej, 0);
    k_edge<<<BATCH*NPTS/4, 128>>>(64);
    k_gnstats<<<BATCH*2, 256>>>(2, 64, g2, b2);
    k_edge_final<<<BATCH*NPTS*64/256, 256>>>(64, 64, 1);

    // Layer 3
    k_key_gemm_tc<<<dim3(16,16,BATCH), 256>>>(64);
    cudaEventRecord(ef, 0);
    cudaStreamWaitEvent(s2, ef, 0);
    k_prep<<<BATCH*NPTS/16, 128, 0, s2>>>(2, 0, 64, 64, 128, x);
    cudaEventRecord(ej, s2);
    k_knn_g<<<BATCH*NPTS/8, 256>>>();
    cudaStreamWaitEvent(0, ej, 0);
    k_edge<<<BATCH*NPTS/2, 128>>>(128);
    k_gnstats<<<BATCH*4, 256>>>(4, 128, g3, b3);
    k_edge_final<<<BATCH*NPTS*128/256, 256>>>(128, 128, 0);

    // fork: featsT (needs only feats) overlaps with MLP head
    cudaEventRecord(ef, 0);
    cudaStreamWaitEvent(s2, ef, 0);
    k_featsT<<<dim3(FEAT/32, NPTS/32, BATCH), dim3(32, 8), 0, s2>>>(out + BATCH*MLPO);
    cudaEventRecord(ej, s2);

    k_mlp_gemm_tc<<<dim3(MLPO/128, BATCH*NPTS/128), 256>>>(Wm, bm);
    k_mlp_part<<<dim3(8, 8, BATCH), 128>>>();
    k_mlp_final<<<BATCH*8, 128>>>(gm, bg, out);

    cudaStreamWaitEvent(0, ej, 0);   // join featsT before capture end
}